// round 12
// baseline (speedup 1.0000x reference)
#include <cuda_runtime.h>
#include <cuda_bf16.h>
#include <math.h>
#include <stdint.h>

// Problem constants
#define EB 1024     // embed dim
#define DH 64       // head dim
#define NH 16       // heads
#define BB 8
#define LL 4096
#define MT (BB*LL)          // 32768 tokens
#define GNP 2176            // padded N (17 tiles of 128)
#define GK EB

// ---------------- scratch ----------------
__device__ float g_a [ (size_t)MT * EB ];
__device__ float g_b [ (size_t)MT * EB ];
__device__ float g_hs[ (size_t)MT * EB ];
__device__ float g_dx[ (size_t)MT * DH ];
__device__ float g_wt[ (size_t)GNP * GK ];  // weights [n][k], tf32-rounded
__device__ float g_et[ (size_t)MT * GK ];   // emb, tf32-rounded

#define SCH 32
#define SCL (LL / SCH)      // 128
__device__ float g_cp[128 * SCH * 64];
__device__ float g_cq[128 * SCH * 64];

// ---------------- helpers ----------------
__device__ __forceinline__ uint32_t smem_u32(const void* p) {
    uint32_t r;
    asm("{ .reg .u64 t; cvta.to.shared.u64 t, %1; cvt.u32.u64 %0, t; }" : "=r"(r) : "l"(p));
    return r;
}
__device__ __forceinline__ void cp_async16(uint32_t dst, const void* src) {
    asm volatile("cp.async.cg.shared.global [%0], [%1], 16;" :: "r"(dst), "l"(src) : "memory");
}
__device__ __forceinline__ void cp_commit() {
    asm volatile("cp.async.commit_group;" ::: "memory");
}
__device__ __forceinline__ uint32_t tf32u(float x) {
    uint32_t u;
    asm("cvt.rna.tf32.f32 %0, %1;" : "=r"(u) : "f"(x));
    return u;
}
__device__ __forceinline__ void mma_tf32(float* c,
                                         uint32_t a0, uint32_t a1, uint32_t a2, uint32_t a3,
                                         uint32_t b0, uint32_t b1) {
    asm volatile(
        "mma.sync.aligned.m16n8k8.row.col.f32.tf32.tf32.f32 "
        "{%0,%1,%2,%3}, {%4,%5,%6,%7}, {%8,%9}, {%0,%1,%2,%3};"
        : "+f"(c[0]), "+f"(c[1]), "+f"(c[2]), "+f"(c[3])
        : "r"(a0), "r"(a1), "r"(a2), "r"(a3), "r"(b0), "r"(b1));
}
__device__ __forceinline__ float tanh_fast(float x) {
    float xc = fminf(fmaxf(x, -10.f), 10.f);
    float t  = __expf(2.f * xc);
    return __fdividef(t - 1.f, t + 1.f);
}

// cp.async with compile-time-immediate smem and gmem offsets
template<int SOFF, int GOFF>
__device__ __forceinline__ void cp_imm(uint32_t cpA, const char* src) {
    asm volatile("cp.async.cg.shared.global [%0+%2], [%1+%3], 16;"
        :: "r"(cpA), "l"(src), "n"(SOFF), "n"(GOFF) : "memory");
}

// ---------------- launch 0: pre-round emb to tf32 ----------------
__global__ void preround_kernel(const float* __restrict__ emb)
{
    size_t i = ((size_t)blockIdx.x * 256 + threadIdx.x) * 4;
    float4 x = *(const float4*)(emb + i);
    float4 y;
    y.x = __uint_as_float(tf32u(x.x));
    y.y = __uint_as_float(tf32u(x.y));
    y.z = __uint_as_float(tf32u(x.z));
    y.w = __uint_as_float(tf32u(x.w));
    *(float4*)(g_et + i) = y;
}

// ---------------- launches 1,2: pack weights [n][k] ----------------
__global__ void pack_a_kernel(const float* __restrict__ Wa)
{
    size_t idx = (size_t)blockIdx.x * 256 + threadIdx.x;
    int n = (int)(idx >> 10);
    int k = (int)(idx & 1023);
    float v = Wa[(size_t)(n >> 6) * (EB * DH) + (size_t)k * DH + (n & 63)];
    g_wt[idx] = __uint_as_float(tf32u(v));
}
__global__ void pack_bd_kernel(const float* __restrict__ Wb, const float* __restrict__ Wd)
{
    size_t idx = (size_t)blockIdx.x * 256 + threadIdx.x;
    int n = (int)(idx >> 10);
    int k = (int)(idx & 1023);
    float v;
    if (n < 1024) {
        v = Wb[(size_t)(n >> 6) * (EB * DH) + (size_t)k * DH + (n & 63)];
    } else {
        int n2 = n - 1024;
        v = (n2 < 64) ? Wd[(size_t)k * DH + n2] : 0.f;
    }
    g_wt[(size_t)(1024 + n) * 1024 + k] = __uint_as_float(tf32u(v));
}

// ---------------- launch 3: TF32 gates GEMM, immediate-addressed mainloop ----------------
#define KC 32
#define NKC (GK / KC)          // 32
#define ROWB 128
#define TILEB (128 * ROWB)     // 16384
#define STAGEB (2 * TILEB)     // A + B = 32768
#define GEMM_SMEM (3 * STAGEB) // 98304 (>= epilogue sD 67584)

// issue the 8 cp.asyncs of one stage with all-constant offsets
template<int PS, int DK>
__device__ __forceinline__ void gemm_prefetch_imm(uint32_t cpA,
                                                  const char* rAa, const char* rBa)
{
    cp_imm<PS * STAGEB + 0 * 4096,          0 * 131072 + DK * 128>(cpA, rAa);
    cp_imm<PS * STAGEB + TILEB + 0 * 4096,  0 * 131072 + DK * 128>(cpA, rBa);
    cp_imm<PS * STAGEB + 1 * 4096,          1 * 131072 + DK * 128>(cpA, rAa);
    cp_imm<PS * STAGEB + TILEB + 1 * 4096,  1 * 131072 + DK * 128>(cpA, rBa);
    cp_imm<PS * STAGEB + 2 * 4096,          2 * 131072 + DK * 128>(cpA, rAa);
    cp_imm<PS * STAGEB + TILEB + 2 * 4096,  2 * 131072 + DK * 128>(cpA, rBa);
    cp_imm<PS * STAGEB + 3 * 4096,          3 * 131072 + DK * 128>(cpA, rAa);
    cp_imm<PS * STAGEB + TILEB + 3 * 4096,  3 * 131072 + DK * 128>(cpA, rBa);
    cp_commit();
}

// body: wait(WN), barrier, optional prefetch(stage PS, triple-local k DK), compute stage S.
template<int S, int PS, int DK, bool PF, int WN>
__device__ __forceinline__ void gemm_body(const char* aP0, const char* aP1,
                                          const char* bP0, const char* bP1,
                                          uint32_t cpA,
                                          const char* rAa, const char* rBa,
                                          float acc[2][8][4])
{
    asm volatile("cp.async.wait_group %0;" :: "n"(WN) : "memory");
    __syncthreads();
    if (PF) gemm_prefetch_imm<PS, DK>(cpA, rAa, rBa);
#pragma unroll
    for (int k16 = 0; k16 < 2; k16++) {
        const char* aP = k16 ? aP1 : aP0;
        const char* bP = k16 ? bP1 : bP0;
        uint32_t aw[2][2][4];
#pragma unroll
        for (int mt = 0; mt < 2; mt++)
#pragma unroll
            for (int hh = 0; hh < 2; hh++) {
                const uint4 v = *(const uint4*)(aP + S * STAGEB + mt * 2048 + hh * 1024);
                aw[mt][hh][0] = v.x; aw[mt][hh][1] = v.y;
                aw[mt][hh][2] = v.z; aw[mt][hh][3] = v.w;
            }
#pragma unroll
        for (int g = 0; g < 8; g++) {
            const uint4 bv = *(const uint4*)(bP + S * STAGEB + g * 1024);
            mma_tf32(acc[0][g], aw[0][0][0], aw[0][1][0], aw[0][0][1], aw[0][1][1], bv.x, bv.y);
            mma_tf32(acc[0][g], aw[0][0][2], aw[0][1][2], aw[0][0][3], aw[0][1][3], bv.z, bv.w);
            mma_tf32(acc[1][g], aw[1][0][0], aw[1][1][0], aw[1][0][1], aw[1][1][1], bv.x, bv.y);
            mma_tf32(acc[1][g], aw[1][0][2], aw[1][1][2], aw[1][0][3], aw[1][1][3], bv.z, bv.w);
        }
    }
}

__global__ void __launch_bounds__(256)
gemm_tf32_kernel(const float* __restrict__ ba,
                 const float* __restrict__ bb,
                 const float* __restrict__ bd)
{
    extern __shared__ char sm_raw[];
    const int tid  = threadIdx.x;
    const int wid  = tid >> 5;
    const int lane = tid & 31;
    const uint32_t sbase = smem_u32(sm_raw);

    const long m0 = (long)blockIdx.y * 128;
    const int  n0 = blockIdx.x * 128;
    const int  wm = (wid & 3) * 32;
    const int  wn = (wid >> 2) * 64;

    const int lrow4 = lane >> 2;
    const int lch   = lane & 3;
    const int par   = (lrow4 & 1) << 2;
    const int ch0   = (lch) ^ par;          // k16 = 0
    const int ch1   = (4 + lch) ^ par;      // k16 = 1

    // fragment base pointers (thread-constant)
    const char* aP0 = sm_raw + (wm + lrow4) * 128 + ch0 * 16;
    const char* aP1 = sm_raw + (wm + lrow4) * 128 + ch1 * 16;
    const char* bP0 = sm_raw + TILEB + (wn + lrow4) * 128 + ch0 * 16;
    const char* bP1 = sm_raw + TILEB + (wn + lrow4) * 128 + ch1 * 16;

    // cp.async dst base (thread-constant)
    const int crow = tid >> 3;
    const int cc   = tid & 7;
    const uint32_t cpA = sbase + crow * 128 + ((cc ^ ((crow & 1) << 2)) << 4);

    // global src bases, advanced 384B per triple
    const char* rAa = (const char*)(g_et + (size_t)m0 * GK) + (size_t)crow * 4096 + cc * 16;
    const char* rBa = (const char*)(g_wt + (size_t)n0 * GK) + (size_t)crow * 4096 + cc * 16;

    float acc[2][8][4];
#pragma unroll
    for (int i = 0; i < 2; i++)
#pragma unroll
        for (int j = 0; j < 8; j++)
#pragma unroll
            for (int q = 0; q < 4; q++) acc[i][j][q] = 0.f;

    // prologue: stage0 <- kc0, stage1 <- kc1
    gemm_prefetch_imm<0, 0>(cpA, rAa, rBa);
    gemm_prefetch_imm<1, 1>(cpA, rAa, rBa);

    // 10 triples: kc = 0..29
#pragma unroll 1
    for (int t = 0; t < 10; t++) {
        gemm_body<0, 2, 2, true, 1>(aP0, aP1, bP0, bP1, cpA, rAa, rBa, acc);
        gemm_body<1, 0, 3, true, 1>(aP0, aP1, bP0, bP1, cpA, rAa, rBa, acc);
        gemm_body<2, 1, 4, true, 1>(aP0, aP1, bP0, bP1, cpA, rAa, rBa, acc);
        rAa += 384;
        rBa += 384;
    }
    // tails: kc = 30 (stage 0), kc = 31 (stage 1)
    gemm_body<0, 0, 0, false, 1>(aP0, aP1, bP0, bP1, cpA, rAa, rBa, acc);
    gemm_body<1, 0, 0, false, 0>(aP0, aP1, bP0, bP1, cpA, rAa, rBa, acc);
    __syncthreads();

    // ---- epilogue ----
    float* sD = (float*)sm_raw;   // 128 x 132
#pragma unroll
    for (int mt = 0; mt < 2; mt++) {
#pragma unroll
        for (int g = 0; g < 8; g++) {
            int ml = wm + mt * 16 + (lane >> 2);
            int nl = wn + g * 8 + (lane & 3) * 2;
            *(float2*)&sD[ml * 132 + nl]       = make_float2(acc[mt][g][0], acc[mt][g][1]);
            *(float2*)&sD[(ml + 8) * 132 + nl] = make_float2(acc[mt][g][2], acc[mt][g][3]);
        }
    }
    __syncthreads();

    for (int i = tid; i < 128 * 128; i += 256) {
        int mm = i >> 7;
        int nn = i & 127;
        int ng = n0 + nn;
        float c = sD[mm * 132 + nn];
        long m = m0 + mm;
        if (ng < 1024) {
            g_a[m * EB + ng] = tanh_fast(c + ba[ng]);
        } else if (ng < 2048) {
            g_b[m * EB + (ng - 1024)] = c + bb[ng - 1024];
        } else if (ng < 2112) {
            g_dx[m * DH + (ng - 2048)] = c + bd[ng - 2048];
        }
    }
}

// ---------------- chunked scan ----------------
__global__ void __launch_bounds__(1024)
scanA_kernel()
{
    const int b = blockIdx.x >> 5;
    const int c = blockIdx.x & 31;
    const int e = threadIdx.x;
    size_t base = ((size_t)b * LL + (size_t)c * SCL) * EB + e;
    float P = 1.f, Q = 0.f;
#pragma unroll 8
    for (int l = 0; l < SCL; l++) {
        size_t idx = base + (size_t)l * EB;
        float av = g_a[idx];
        float bv = g_b[idx];
        Q = fmaf(av, Q, bv);
        P *= av;
    }
    int bh = b * 16 + (e >> 6);
    g_cp[(bh * SCH + c) * 64 + (e & 63)] = P;
    g_cq[(bh * SCH + c) * 64 + (e & 63)] = Q;
}

__global__ void __launch_bounds__(1024)
scanC_kernel()
{
    const int b = blockIdx.x >> 5;
    const int c = blockIdx.x & 31;
    const int e = threadIdx.x;
    const int bh = b * 16 + (e >> 6);
    const int d  = e & 63;
    float hv = 0.f;
    for (int cc = 0; cc < c; cc++) {
        int i = (bh * SCH + cc) * 64 + d;
        hv = fmaf(g_cp[i], hv, g_cq[i]);
    }
    size_t base = ((size_t)b * LL + (size_t)c * SCL) * EB + e;
#pragma unroll 8
    for (int l = 0; l < SCL; l++) {
        size_t idx = base + (size_t)l * EB;
        float av = g_a[idx];
        float bv = g_b[idx];
        hv = fmaf(av, hv, bv);
        g_hs[idx] = hv;
    }
}

// ---------------- fused per-token epilogue ----------------
#define TOK 64
#define HS_STRIDE 68
#define POST_FLOATS 21248
#define POST_BYTES  (POST_FLOATS * 4)

__device__ __forceinline__ float grp8_sum(float v) {
    v += __shfl_xor_sync(0xffffffffu, v, 1);
    v += __shfl_xor_sync(0xffffffffu, v, 2);
    v += __shfl_xor_sync(0xffffffffu, v, 4);
    return v;
}

__device__ __forceinline__ void post_prefetch(uint32_t swc, uint32_t shs,
                                              const float* __restrict__ Wc,
                                              int h, long token0, int tid)
{
    const char* wsrc = (const char*)(Wc + (size_t)h * 4096);
#pragma unroll
    for (int i = 0; i < 4; i++) {
        int idx = tid + i * 256;
        cp_async16(swc + idx * 16, wsrc + idx * 16);
    }
#pragma unroll
    for (int i = 0; i < 4; i++) {
        int idx = tid + i * 256;
        int t = idx >> 4;
        int c = idx & 15;
        const char* hsrc = (const char*)(g_hs + (token0 + t) * (size_t)EB + h * 64);
        cp_async16(shs + (uint32_t)(t * HS_STRIDE * 4 + c * 16), hsrc + c * 16);
    }
}

__global__ void __launch_bounds__(256)
post_kernel(const float* __restrict__ Wc,  const float* __restrict__ bc,
            const float* __restrict__ head_w,
            const float* __restrict__ hn_g, const float* __restrict__ hn_b,
            const float* __restrict__ W1,  const float* __restrict__ b1,
            const float* __restrict__ W2,  const float* __restrict__ b2,
            const float* __restrict__ Wp,  const float* __restrict__ bp,
            const float* __restrict__ ng,  const float* __restrict__ nb,
            float* __restrict__ out)
{
    extern __shared__ float sm[];
    const int tid = threadIdx.x;
    const int tt  = tid >> 3;
    const int eg  = tid & 7;
    const int e0  = eg * 8;
    const long token0 = (long)blockIdx.x * TOK;
    const long tok0 = token0 + tt;
    const long tok1 = token0 + tt + 32;

    const uint32_t swc_u0 = smem_u32(sm);
    const uint32_t swc_u1 = smem_u32(sm + 4096);
    const uint32_t shs_u0 = smem_u32(sm + 8192);
    const uint32_t shs_u1 = smem_u32(sm + 8192 + TOK * HS_STRIDE);

    float dxv0[8], dxv1[8], acc0[8], acc1[8];
#pragma unroll
    for (int k = 0; k < 8; k++) {
        dxv0[k] = g_dx[tok0 * DH + e0 + k];
        dxv1[k] = g_dx[tok1 * DH + e0 + k];
        acc0[k] = dxv0[k];
        acc1[k] = dxv1[k];
    }

    post_prefetch(swc_u0, shs_u0, Wc, 0, token0, tid);
    cp_commit();

    for (int h = 0; h < NH; h++) {
        const int cur = h & 1;
        if (h + 1 < NH) {
            post_prefetch(cur ? swc_u0 : swc_u1, cur ? shs_u0 : shs_u1, Wc, h + 1, token0, tid);
            cp_commit();
            asm volatile("cp.async.wait_group 1;" ::: "memory");
        } else {
            asm volatile("cp.async.wait_group 0;" ::: "memory");
        }
        __syncthreads();

        const float* sWc = sm + (cur ? 4096 : 0);
        const float* sHs = sm + 8192 + (cur ? TOK * HS_STRIDE : 0);

        float o0[8], o1[8];
#pragma unroll
        for (int k = 0; k < 8; k++) {
            float bck = bc[h * DH + e0 + k];
            o0[k] = bck + dxv0[k];
            o1[k] = bck + dxv1[k];
        }
#pragma unroll 8
        for (int d = 0; d < 64; d++) {
            float hv0 = sHs[tt * HS_STRIDE + d];
            float hv1 = sHs[(tt + 32) * HS_STRIDE + d];
            float4 w0 = *(const float4*)&sWc[d * 64 + e0];
            float4 w1 = *(const float4*)&sWc[d * 64 + e0 + 4];
            o0[0] = fmaf(hv0, w0.x, o0[0]); o0[1] = fmaf(hv0, w0.y, o0[1]);
            o0[2] = fmaf(hv0, w0.z, o0[2]); o0[3] = fmaf(hv0, w0.w, o0[3]);
            o0[4] = fmaf(hv0, w1.x, o0[4]); o0[5] = fmaf(hv0, w1.y, o0[5]);
            o0[6] = fmaf(hv0, w1.z, o0[6]); o0[7] = fmaf(hv0, w1.w, o0[7]);
            o1[0] = fmaf(hv1, w0.x, o1[0]); o1[1] = fmaf(hv1, w0.y, o1[1]);
            o1[2] = fmaf(hv1, w0.z, o1[2]); o1[3] = fmaf(hv1, w0.w, o1[3]);
            o1[4] = fmaf(hv1, w1.x, o1[4]); o1[5] = fmaf(hv1, w1.y, o1[5]);
            o1[6] = fmaf(hv1, w1.z, o1[6]); o1[7] = fmaf(hv1, w1.w, o1[7]);
        }
        float s10 = 0.f, s20 = 0.f, s11 = 0.f, s21 = 0.f;
#pragma unroll
        for (int k = 0; k < 8; k++) {
            s10 += o0[k]; s20 += o0[k] * o0[k];
            s11 += o1[k]; s21 += o1[k] * o1[k];
        }
        s10 = grp8_sum(s10); s20 = grp8_sum(s20);
        s11 = grp8_sum(s11); s21 = grp8_sum(s21);
        float mean0 = s10 * (1.f / 64.f);
        float var0  = s20 * (1.f / 64.f) - mean0 * mean0;
        float rstd0 = rsqrtf(var0 + 1e-5f);
        float mean1 = s11 * (1.f / 64.f);
        float var1  = s21 * (1.f / 64.f) - mean1 * mean1;
        float rstd1 = rsqrtf(var1 + 1e-5f);
        float hw = head_w[h];
#pragma unroll
        for (int k = 0; k < 8; k++) {
            float gk = hn_g[h * DH + e0 + k];
            float bk = hn_b[h * DH + e0 + k];
            acc0[k] = fmaf(hw, (o0[k] - mean0) * rstd0 * gk + bk, acc0[k]);
            acc1[k] = fmaf(hw, (o1[k] - mean1) * rstd1 * gk + bk, acc1[k]);
        }
        __syncthreads();
    }

    float u0[8], u1[8];
    {
        float s10 = 0.f, s20 = 0.f, s11 = 0.f, s21 = 0.f;
#pragma unroll
        for (int k = 0; k < 8; k++) {
            acc0[k] *= (1.f / (float)NH);
            acc1[k] *= (1.f / (float)NH);
            s10 += acc0[k]; s20 += acc0[k] * acc0[k];
            s11 += acc1[k]; s21 += acc1[k] * acc1[k];
        }
        s10 = grp8_sum(s10); s20 = grp8_sum(s20);
        s11 = grp8_sum(s11); s21 = grp8_sum(s21);
        float mean0 = s10 * (1.f / 64.f);
        float var0  = s20 * (1.f / 64.f) - mean0 * mean0;
        float rstd0 = rsqrtf(var0 + 1e-5f);
        float mean1 = s11 * (1.f / 64.f);
        float var1  = s21 * (1.f / 64.f) - mean1 * mean1;
        float rstd1 = rsqrtf(var1 + 1e-5f);
#pragma unroll
        for (int k = 0; k < 8; k++) {
            float ngk = ng[e0 + k], nbk = nb[e0 + k];
            u0[k] = acc0[k] + (acc0[k] - mean0) * rstd0 * ngk + nbk;
            u1[k] = acc1[k] + (acc1[k] - mean1) * rstd1 * ngk + nbk;
        }
    }

    __syncthreads();

    float* sW1c = sm;
    float* sW2c = sm + 4096;
    float* sU   = sm + 8192;
    float* sGc  = sm + 8192 + TOK * HS_STRIDE;
    float* sHo  = sm + 8192 + 2 * TOK * HS_STRIDE;

#pragma unroll
    for (int k = 0; k < 8; k++) {
        sU[tt * HS_STRIDE + e0 + k]        = u0[k];
        sU[(tt + 32) * HS_STRIDE + e0 + k] = u1[k];
    }

    float o20[8], o21[8];
#pragma unroll
    for (int k = 0; k < 8; k++) { o20[k] = b2[e0 + k]; o21[k] = o20[k]; }

    for (int jc = 0; jc < 4; jc++) {
        __syncthreads();
#pragma unroll
        for (int i = 0; i < 16; i++) {
            int idx = tid + i * 256;
            int d = idx >> 6, jj = idx & 63;
            sW1c[idx] = W1[d * 256 + jc * 64 + jj];
            sW2c[idx] = W2[(jc * 64 + (idx >> 6)) * 64 + (idx & 63)];
        }
        __syncthreads();
#pragma unroll
        for (int kk = 0; kk < 8; kk++) {
            int jl = eg + 8 * kk;
            float m0 = b1[jc * 64 + jl], m1 = m0;
#pragma unroll 8
            for (int d = 0; d < 64; d++) {
                float w = sW1c[d * 64 + jl];
                m0 = fmaf(sU[tt * HS_STRIDE + d], w, m0);
                m1 = fmaf(sU[(tt + 32) * HS_STRIDE + d], w, m1);
            }
            sGc[tt * HS_STRIDE + jl]        = 0.5f * m0 * (1.f + erff(m0 * 0.70710678118654752f));
            sGc[(tt + 32) * HS_STRIDE + jl] = 0.5f * m1 * (1.f + erff(m1 * 0.70710678118654752f));
        }
        __syncthreads();
#pragma unroll 8
        for (int jj = 0; jj < 64; jj++) {
            float gv0 = sGc[tt * HS_STRIDE + jj];
            float gv1 = sGc[(tt + 32) * HS_STRIDE + jj];
            float4 w0 = *(const float4*)&sW2c[jj * 64 + e0];
            float4 w1 = *(const float4*)&sW2c[jj * 64 + e0 + 4];
            o20[0] = fmaf(gv0, w0.x, o20[0]); o20[1] = fmaf(gv0, w0.y, o20[1]);
            o20[2] = fmaf(gv0, w0.z, o20[2]); o20[3] = fmaf(gv0, w0.w, o20[3]);
            o20[4] = fmaf(gv0, w1.x, o20[4]); o20[5] = fmaf(gv0, w1.y, o20[5]);
            o20[6] = fmaf(gv0, w1.z, o20[6]); o20[7] = fmaf(gv0, w1.w, o20[7]);
            o21[0] = fmaf(gv1, w0.x, o21[0]); o21[1] = fmaf(gv1, w0.y, o21[1]);
            o21[2] = fmaf(gv1, w0.z, o21[2]); o21[3] = fmaf(gv1, w0.w, o21[3]);
            o21[4] = fmaf(gv1, w1.x, o21[4]); o21[5] = fmaf(gv1, w1.y, o21[5]);
            o21[6] = fmaf(gv1, w1.z, o21[6]); o21[7] = fmaf(gv1, w1.w, o21[7]);
        }
    }

    __syncthreads();
#pragma unroll
    for (int k = 0; k < 8; k++) {
        sHo[tt * HS_STRIDE + e0 + k]        = u0[k] + o20[k];
        sHo[(tt + 32) * HS_STRIDE + e0 + k] = u1[k] + o21[k];
    }

    float fo0[8], fo1[8];
#pragma unroll
    for (int k = 0; k < 8; k++) { fo0[k] = bp[e0 + k]; fo1[k] = fo0[k]; }
    for (int dc = 0; dc < 2; dc++) {
        __syncthreads();
#pragma unroll
        for (int i = 0; i < 8; i++) {
            int idx = tid + i * 256;
            int d = idx >> 6, e = idx & 63;
            sW1c[idx] = Wp[(dc * 32 + d) * 64 + e];
        }
        __syncthreads();
#pragma unroll 8
        for (int d = 0; d < 32; d++) {
            float hv0 = sHo[tt * HS_STRIDE + dc * 32 + d];
            float hv1 = sHo[(tt + 32) * HS_STRIDE + dc * 32 + d];
            float4 w0 = *(const float4*)&sW1c[d * 64 + e0];
            float4 w1 = *(const float4*)&sW1c[d * 64 + e0 + 4];
            fo0[0] = fmaf(hv0, w0.x, fo0[0]); fo0[1] = fmaf(hv0, w0.y, fo0[1]);
            fo0[2] = fmaf(hv0, w0.z, fo0[2]); fo0[3] = fmaf(hv0, w0.w, fo0[3]);
            fo0[4] = fmaf(hv0, w1.x, fo0[4]); fo0[5] = fmaf(hv0, w1.y, fo0[5]);
            fo0[6] = fmaf(hv0, w1.z, fo0[6]); fo0[7] = fmaf(hv0, w1.w, fo0[7]);
            fo1[0] = fmaf(hv1, w0.x, fo1[0]); fo1[1] = fmaf(hv1, w0.y, fo1[1]);
            fo1[2] = fmaf(hv1, w0.z, fo1[2]); fo1[3] = fmaf(hv1, w0.w, fo1[3]);
            fo1[4] = fmaf(hv1, w1.x, fo1[4]); fo1[5] = fmaf(hv1, w1.y, fo1[5]);
            fo1[6] = fmaf(hv1, w1.z, fo1[6]); fo1[7] = fmaf(hv1, w1.w, fo1[7]);
        }
    }
#pragma unroll
    for (int k = 0; k < 8; k++) {
        out[tok0 * DH + e0 + k] = fo0[k];
        out[tok1 * DH + e0 + k] = fo1[k];
    }
}

// ---------------- launch ----------------
extern "C" void kernel_launch(void* const* d_in, const int* in_sizes, int n_in,
                              void* d_out, int out_size)
{
    const float* emb    = (const float*)d_in[0];
    const float* Wa     = (const float*)d_in[1];
    const float* ba     = (const float*)d_in[2];
    const float* Wb     = (const float*)d_in[3];
    const float* bb     = (const float*)d_in[4];
    const float* Wc     = (const float*)d_in[5];
    const float* bc     = (const float*)d_in[6];
    const float* head_w = (const float*)d_in[7];
    const float* hn_g   = (const float*)d_in[8];
    const float* hn_b   = (const float*)d_in[9];
    const float* Wd     = (const float*)d_in[10];
    const float* bd     = (const float*)d_in[11];
    const float* W1     = (const float*)d_in[12];
    const float* b1     = (const float*)d_in[13];
    const float* W2     = (const float*)d_in[14];
    const float* b2     = (const float*)d_in[15];
    const float* Wp     = (const float*)d_in[16];
    const float* bp     = (const float*)d_in[17];
    const float* ng     = (const float*)d_in[18];
    const float* nb     = (const float*)d_in[19];
    float* out = (float*)d_out;

    cudaFuncSetAttribute(gemm_tf32_kernel, cudaFuncAttributeMaxDynamicSharedMemorySize, GEMM_SMEM);
    cudaFuncSetAttribute(post_kernel, cudaFuncAttributeMaxDynamicSharedMemorySize, POST_BYTES);

    preround_kernel<<<(int)((size_t)MT * GK / 4 / 256), 256>>>(emb);
    pack_a_kernel<<<4096, 256>>>(Wa);
    pack_bd_kernel<<<4608, 256>>>(Wb, Wd);

    dim3 ggrid(GNP / 128, MT / 128);
    gemm_tf32_kernel<<<ggrid, 256, GEMM_SMEM>>>(ba, bb, bd);

    scanA_kernel<<<BB * SCH, 1024>>>();
    scanC_kernel<<<BB * SCH, 1024>>>();

    post_kernel<<<MT / TOK, 256, POST_BYTES>>>(Wc, bc, head_w, hn_g, hn_b,
                                               W1, b1, W2, b2, Wp, bp, ng, nb, out);
}

// round 13
// speedup vs baseline: 1.0997x; 1.0997x over previous
#include <cuda_runtime.h>
#include <cuda_bf16.h>
#include <math.h>
#include <stdint.h>

// Problem constants
#define EB 1024     // embed dim
#define DH 64       // head dim
#define NH 16       // heads
#define BB 8
#define LL 4096
#define MT (BB*LL)          // 32768 tokens
#define GNP 2176            // padded N (17 tiles of 128)
#define GK EB

// ---------------- scratch ----------------
__device__ float g_a [ (size_t)MT * EB ];
__device__ float g_b [ (size_t)MT * EB ];
__device__ float g_hs[ (size_t)MT * EB ];
__device__ float g_dx[ (size_t)MT * DH ];
__device__ float g_wt[ (size_t)GNP * GK ];  // weights [n][k], tf32-rounded
__device__ float g_et[ (size_t)MT * GK ];   // emb, tf32-rounded

#define SCH 32
#define SCL (LL / SCH)      // 128
__device__ float g_cp[128 * SCH * 64];
__device__ float g_cq[128 * SCH * 64];

// ---------------- helpers ----------------
__device__ __forceinline__ uint32_t smem_u32(const void* p) {
    uint32_t r;
    asm("{ .reg .u64 t; cvta.to.shared.u64 t, %1; cvt.u32.u64 %0, t; }" : "=r"(r) : "l"(p));
    return r;
}
__device__ __forceinline__ void cp_async16(uint32_t dst, const void* src) {
    asm volatile("cp.async.cg.shared.global [%0], [%1], 16;" :: "r"(dst), "l"(src) : "memory");
}
__device__ __forceinline__ void cp_commit() {
    asm volatile("cp.async.commit_group;" ::: "memory");
}
__device__ __forceinline__ uint32_t tf32u(float x) {
    uint32_t u;
    asm("cvt.rna.tf32.f32 %0, %1;" : "=r"(u) : "f"(x));
    return u;
}
__device__ __forceinline__ void mma_tf32(float* c,
                                         uint32_t a0, uint32_t a1, uint32_t a2, uint32_t a3,
                                         uint32_t b0, uint32_t b1) {
    asm volatile(
        "mma.sync.aligned.m16n8k8.row.col.f32.tf32.tf32.f32 "
        "{%0,%1,%2,%3}, {%4,%5,%6,%7}, {%8,%9}, {%0,%1,%2,%3};"
        : "+f"(c[0]), "+f"(c[1]), "+f"(c[2]), "+f"(c[3])
        : "r"(a0), "r"(a1), "r"(a2), "r"(a3), "r"(b0), "r"(b1));
}
__device__ __forceinline__ float tanh_fast(float x) {
    float xc = fminf(fmaxf(x, -10.f), 10.f);
    float t  = __expf(2.f * xc);
    return __fdividef(t - 1.f, t + 1.f);
}

// ---------------- launch 0: pre-round emb to tf32 ----------------
__global__ void preround_kernel(const float* __restrict__ emb)
{
    size_t i = ((size_t)blockIdx.x * 256 + threadIdx.x) * 4;
    float4 x = *(const float4*)(emb + i);
    float4 y;
    y.x = __uint_as_float(tf32u(x.x));
    y.y = __uint_as_float(tf32u(x.y));
    y.z = __uint_as_float(tf32u(x.z));
    y.w = __uint_as_float(tf32u(x.w));
    *(float4*)(g_et + i) = y;
}

// ---------------- launches 1,2: pack weights [n][k] ----------------
__global__ void pack_a_kernel(const float* __restrict__ Wa)
{
    size_t idx = (size_t)blockIdx.x * 256 + threadIdx.x;
    int n = (int)(idx >> 10);
    int k = (int)(idx & 1023);
    float v = Wa[(size_t)(n >> 6) * (EB * DH) + (size_t)k * DH + (n & 63)];
    g_wt[idx] = __uint_as_float(tf32u(v));
}
__global__ void pack_bd_kernel(const float* __restrict__ Wb, const float* __restrict__ Wd)
{
    size_t idx = (size_t)blockIdx.x * 256 + threadIdx.x;
    int n = (int)(idx >> 10);
    int k = (int)(idx & 1023);
    float v;
    if (n < 1024) {
        v = Wb[(size_t)(n >> 6) * (EB * DH) + (size_t)k * DH + (n & 63)];
    } else {
        int n2 = n - 1024;
        v = (n2 < 64) ? Wd[(size_t)k * DH + n2] : 0.f;
    }
    g_wt[(size_t)(1024 + n) * 1024 + k] = __uint_as_float(tf32u(v));
}

// ---------------- launch 3: TF32 gates GEMM, CTA 128x128, warp 32x64 ----------------
#define KC 32
#define NKC (GK / KC)          // 32
#define ROWB 128
#define TILEB (128 * ROWB)     // 16384
#define STAGEB (2 * TILEB)     // A + B = 32768
#define GEMM_SMEM (3 * STAGEB) // 98304 (>= epilogue sD 67584)

#define SWZ(row, chunk) ((uint32_t)((row) * ROWB + ((((chunk) ^ (((row) & 1) << 2))) << 4)))

__device__ __forceinline__ void gemm_load_stage(uint32_t sst, int kc, int tid,
                                                const char* Ag, const char* Bg)
{
    const size_t kb = (size_t)kc * 128;
#pragma unroll
    for (int j = 0; j < 4; j++) {
        int id  = tid + j * 256;
        int row = id >> 3;
        int c   = id & 7;
        cp_async16(sst + SWZ(row, c),         Ag + (size_t)row * 4096 + kb + c * 16);
        cp_async16(sst + TILEB + SWZ(row, c), Bg + (size_t)row * 4096 + kb + c * 16);
    }
}

__global__ void __launch_bounds__(256, 2)
gemm_tf32_kernel(const float* __restrict__ ba,
                 const float* __restrict__ bb,
                 const float* __restrict__ bd)
{
    extern __shared__ char sm_raw[];
    const int tid  = threadIdx.x;
    const int wid  = tid >> 5;
    const int lane = tid & 31;
    const uint32_t sbase = smem_u32(sm_raw);

    const long m0 = (long)blockIdx.y * 128;
    const int  n0 = blockIdx.x * 128;
    const int  wm = (wid & 3) * 32;
    const int  wn = (wid >> 2) * 64;

    const char* Ag = (const char*)(g_et + (size_t)m0 * GK);
    const char* Bg = (const char*)(g_wt + (size_t)n0 * GK);

    float acc[2][8][4];
#pragma unroll
    for (int i = 0; i < 2; i++)
#pragma unroll
        for (int j = 0; j < 8; j++)
#pragma unroll
            for (int q = 0; q < 4; q++) acc[i][j][q] = 0.f;

    gemm_load_stage(sbase, 0, tid, Ag, Bg);
    cp_commit();
    gemm_load_stage(sbase + STAGEB, 1, tid, Ag, Bg);
    cp_commit();

    const int lrow4 = lane >> 2;
    const int lch   = lane & 3;

    int stage = 0;
#pragma unroll 3
    for (int kc = 0; kc < NKC; kc++) {
        if (kc + 1 < NKC) {
            asm volatile("cp.async.wait_group 1;" ::: "memory");
        } else {
            asm volatile("cp.async.wait_group 0;" ::: "memory");
        }
        __syncthreads();
        if (kc + 2 < NKC) {
            int nstage = stage + 2; if (nstage >= 3) nstage -= 3;
            gemm_load_stage(sbase + nstage * STAGEB, kc + 2, tid, Ag, Bg);
            cp_commit();
        }

        const char* sA = sm_raw + stage * STAGEB;
        const char* sB = sA + TILEB;

#pragma unroll
        for (int k16 = 0; k16 < 2; k16++) {
            const int ch = k16 * 4 + lch;
            uint32_t aw[2][2][4];
#pragma unroll
            for (int mt = 0; mt < 2; mt++) {
#pragma unroll
                for (int hh = 0; hh < 2; hh++) {
                    int row = wm + mt * 16 + hh * 8 + lrow4;
                    const uint4 v = *(const uint4*)(sA + SWZ(row, ch));
                    aw[mt][hh][0] = v.x;
                    aw[mt][hh][1] = v.y;
                    aw[mt][hh][2] = v.z;
                    aw[mt][hh][3] = v.w;
                }
            }
#pragma unroll
            for (int g = 0; g < 8; g++) {
                int row = wn + g * 8 + lrow4;
                const uint4 bv = *(const uint4*)(sB + SWZ(row, ch));
                mma_tf32(acc[0][g], aw[0][0][0], aw[0][1][0], aw[0][0][1], aw[0][1][1], bv.x, bv.y);
                mma_tf32(acc[0][g], aw[0][0][2], aw[0][1][2], aw[0][0][3], aw[0][1][3], bv.z, bv.w);
                mma_tf32(acc[1][g], aw[1][0][0], aw[1][1][0], aw[1][0][1], aw[1][1][1], bv.x, bv.y);
                mma_tf32(acc[1][g], aw[1][0][2], aw[1][1][2], aw[1][0][3], aw[1][1][3], bv.z, bv.w);
            }
        }
        stage++; if (stage == 3) stage = 0;
    }
    __syncthreads();

    // ---- epilogue ----
    float* sD = (float*)sm_raw;   // 128 x 132
#pragma unroll
    for (int mt = 0; mt < 2; mt++) {
#pragma unroll
        for (int g = 0; g < 8; g++) {
            int ml = wm + mt * 16 + (lane >> 2);
            int nl = wn + g * 8 + (lane & 3) * 2;
            *(float2*)&sD[ml * 132 + nl]       = make_float2(acc[mt][g][0], acc[mt][g][1]);
            *(float2*)&sD[(ml + 8) * 132 + nl] = make_float2(acc[mt][g][2], acc[mt][g][3]);
        }
    }
    __syncthreads();

    for (int i = tid; i < 128 * 128; i += 256) {
        int mm = i >> 7;
        int nn = i & 127;
        int ng = n0 + nn;
        float c = sD[mm * 132 + nn];
        long m = m0 + mm;
        if (ng < 1024) {
            __stcs(&g_a[m * EB + ng], tanh_fast(c + ba[ng]));
        } else if (ng < 2048) {
            __stcs(&g_b[m * EB + (ng - 1024)], c + bb[ng - 1024]);
        } else if (ng < 2112) {
            __stcs(&g_dx[m * DH + (ng - 2048)], c + bd[ng - 2048]);
        }
    }
}

// ---------------- chunked scan ----------------
__global__ void __launch_bounds__(1024)
scanA_kernel()
{
    const int b = blockIdx.x >> 5;
    const int c = blockIdx.x & 31;
    const int e = threadIdx.x;
    size_t base = ((size_t)b * LL + (size_t)c * SCL) * EB + e;
    float P = 1.f, Q = 0.f;
#pragma unroll 8
    for (int l = 0; l < SCL; l++) {
        size_t idx = base + (size_t)l * EB;
        float av = __ldcs(&g_a[idx]);
        float bv = __ldcs(&g_b[idx]);
        Q = fmaf(av, Q, bv);
        P *= av;
    }
    int bh = b * 16 + (e >> 6);
    g_cp[(bh * SCH + c) * 64 + (e & 63)] = P;
    g_cq[(bh * SCH + c) * 64 + (e & 63)] = Q;
}

__global__ void __launch_bounds__(1024)
scanC_kernel()
{
    const int b = blockIdx.x >> 5;
    const int c = blockIdx.x & 31;
    const int e = threadIdx.x;
    const int bh = b * 16 + (e >> 6);
    const int d  = e & 63;
    float hv = 0.f;
    for (int cc = 0; cc < c; cc++) {
        int i = (bh * SCH + cc) * 64 + d;
        hv = fmaf(g_cp[i], hv, g_cq[i]);
    }
    size_t base = ((size_t)b * LL + (size_t)c * SCL) * EB + e;
#pragma unroll 8
    for (int l = 0; l < SCL; l++) {
        size_t idx = base + (size_t)l * EB;
        float av = __ldcs(&g_a[idx]);
        float bv = __ldcs(&g_b[idx]);
        hv = fmaf(av, hv, bv);
        g_hs[idx] = hv;
    }
}

// ---------------- fused per-token epilogue ----------------
#define TOK 64
#define HS_STRIDE 68
#define POST_FLOATS 21248
#define POST_BYTES  (POST_FLOATS * 4)

__device__ __forceinline__ float grp8_sum(float v) {
    v += __shfl_xor_sync(0xffffffffu, v, 1);
    v += __shfl_xor_sync(0xffffffffu, v, 2);
    v += __shfl_xor_sync(0xffffffffu, v, 4);
    return v;
}

__device__ __forceinline__ void post_prefetch(uint32_t swc, uint32_t shs,
                                              const float* __restrict__ Wc,
                                              int h, long token0, int tid)
{
    const char* wsrc = (const char*)(Wc + (size_t)h * 4096);
#pragma unroll
    for (int i = 0; i < 4; i++) {
        int idx = tid + i * 256;
        cp_async16(swc + idx * 16, wsrc + idx * 16);
    }
#pragma unroll
    for (int i = 0; i < 4; i++) {
        int idx = tid + i * 256;
        int t = idx >> 4;
        int c = idx & 15;
        const char* hsrc = (const char*)(g_hs + (token0 + t) * (size_t)EB + h * 64);
        cp_async16(shs + (uint32_t)(t * HS_STRIDE * 4 + c * 16), hsrc + c * 16);
    }
}

__global__ void __launch_bounds__(256)
post_kernel(const float* __restrict__ Wc,  const float* __restrict__ bc,
            const float* __restrict__ head_w,
            const float* __restrict__ hn_g, const float* __restrict__ hn_b,
            const float* __restrict__ W1,  const float* __restrict__ b1,
            const float* __restrict__ W2,  const float* __restrict__ b2,
            const float* __restrict__ Wp,  const float* __restrict__ bp,
            const float* __restrict__ ng,  const float* __restrict__ nb,
            float* __restrict__ out)
{
    extern __shared__ float sm[];
    const int tid = threadIdx.x;
    const int tt  = tid >> 3;
    const int eg  = tid & 7;
    const int e0  = eg * 8;
    const long token0 = (long)blockIdx.x * TOK;
    const long tok0 = token0 + tt;
    const long tok1 = token0 + tt + 32;

    const uint32_t swc_u0 = smem_u32(sm);
    const uint32_t swc_u1 = smem_u32(sm + 4096);
    const uint32_t shs_u0 = smem_u32(sm + 8192);
    const uint32_t shs_u1 = smem_u32(sm + 8192 + TOK * HS_STRIDE);

    float dxv0[8], dxv1[8], acc0[8], acc1[8];
#pragma unroll
    for (int k = 0; k < 8; k++) {
        dxv0[k] = g_dx[tok0 * DH + e0 + k];
        dxv1[k] = g_dx[tok1 * DH + e0 + k];
        acc0[k] = dxv0[k];
        acc1[k] = dxv1[k];
    }

    post_prefetch(swc_u0, shs_u0, Wc, 0, token0, tid);
    cp_commit();

    for (int h = 0; h < NH; h++) {
        const int cur = h & 1;
        if (h + 1 < NH) {
            post_prefetch(cur ? swc_u0 : swc_u1, cur ? shs_u0 : shs_u1, Wc, h + 1, token0, tid);
            cp_commit();
            asm volatile("cp.async.wait_group 1;" ::: "memory");
        } else {
            asm volatile("cp.async.wait_group 0;" ::: "memory");
        }
        __syncthreads();

        const float* sWc = sm + (cur ? 4096 : 0);
        const float* sHs = sm + 8192 + (cur ? TOK * HS_STRIDE : 0);

        float o0[8], o1[8];
#pragma unroll
        for (int k = 0; k < 8; k++) {
            float bck = bc[h * DH + e0 + k];
            o0[k] = bck + dxv0[k];
            o1[k] = bck + dxv1[k];
        }
#pragma unroll 8
        for (int d = 0; d < 64; d++) {
            float hv0 = sHs[tt * HS_STRIDE + d];
            float hv1 = sHs[(tt + 32) * HS_STRIDE + d];
            float4 w0 = *(const float4*)&sWc[d * 64 + e0];
            float4 w1 = *(const float4*)&sWc[d * 64 + e0 + 4];
            o0[0] = fmaf(hv0, w0.x, o0[0]); o0[1] = fmaf(hv0, w0.y, o0[1]);
            o0[2] = fmaf(hv0, w0.z, o0[2]); o0[3] = fmaf(hv0, w0.w, o0[3]);
            o0[4] = fmaf(hv0, w1.x, o0[4]); o0[5] = fmaf(hv0, w1.y, o0[5]);
            o0[6] = fmaf(hv0, w1.z, o0[6]); o0[7] = fmaf(hv0, w1.w, o0[7]);
            o1[0] = fmaf(hv1, w0.x, o1[0]); o1[1] = fmaf(hv1, w0.y, o1[1]);
            o1[2] = fmaf(hv1, w0.z, o1[2]); o1[3] = fmaf(hv1, w0.w, o1[3]);
            o1[4] = fmaf(hv1, w1.x, o1[4]); o1[5] = fmaf(hv1, w1.y, o1[5]);
            o1[6] = fmaf(hv1, w1.z, o1[6]); o1[7] = fmaf(hv1, w1.w, o1[7]);
        }
        float s10 = 0.f, s20 = 0.f, s11 = 0.f, s21 = 0.f;
#pragma unroll
        for (int k = 0; k < 8; k++) {
            s10 += o0[k]; s20 += o0[k] * o0[k];
            s11 += o1[k]; s21 += o1[k] * o1[k];
        }
        s10 = grp8_sum(s10); s20 = grp8_sum(s20);
        s11 = grp8_sum(s11); s21 = grp8_sum(s21);
        float mean0 = s10 * (1.f / 64.f);
        float var0  = s20 * (1.f / 64.f) - mean0 * mean0;
        float rstd0 = rsqrtf(var0 + 1e-5f);
        float mean1 = s11 * (1.f / 64.f);
        float var1  = s21 * (1.f / 64.f) - mean1 * mean1;
        float rstd1 = rsqrtf(var1 + 1e-5f);
        float hw = head_w[h];
#pragma unroll
        for (int k = 0; k < 8; k++) {
            float gk = hn_g[h * DH + e0 + k];
            float bk = hn_b[h * DH + e0 + k];
            acc0[k] = fmaf(hw, (o0[k] - mean0) * rstd0 * gk + bk, acc0[k]);
            acc1[k] = fmaf(hw, (o1[k] - mean1) * rstd1 * gk + bk, acc1[k]);
        }
        __syncthreads();
    }

    float u0[8], u1[8];
    {
        float s10 = 0.f, s20 = 0.f, s11 = 0.f, s21 = 0.f;
#pragma unroll
        for (int k = 0; k < 8; k++) {
            acc0[k] *= (1.f / (float)NH);
            acc1[k] *= (1.f / (float)NH);
            s10 += acc0[k]; s20 += acc0[k] * acc0[k];
            s11 += acc1[k]; s21 += acc1[k] * acc1[k];
        }
        s10 = grp8_sum(s10); s20 = grp8_sum(s20);
        s11 = grp8_sum(s11); s21 = grp8_sum(s21);
        float mean0 = s10 * (1.f / 64.f);
        float var0  = s20 * (1.f / 64.f) - mean0 * mean0;
        float rstd0 = rsqrtf(var0 + 1e-5f);
        float mean1 = s11 * (1.f / 64.f);
        float var1  = s21 * (1.f / 64.f) - mean1 * mean1;
        float rstd1 = rsqrtf(var1 + 1e-5f);
#pragma unroll
        for (int k = 0; k < 8; k++) {
            float ngk = ng[e0 + k], nbk = nb[e0 + k];
            u0[k] = acc0[k] + (acc0[k] - mean0) * rstd0 * ngk + nbk;
            u1[k] = acc1[k] + (acc1[k] - mean1) * rstd1 * ngk + nbk;
        }
    }

    __syncthreads();

    float* sW1c = sm;
    float* sW2c = sm + 4096;
    float* sU   = sm + 8192;
    float* sGc  = sm + 8192 + TOK * HS_STRIDE;
    float* sHo  = sm + 8192 + 2 * TOK * HS_STRIDE;

#pragma unroll
    for (int k = 0; k < 8; k++) {
        sU[tt * HS_STRIDE + e0 + k]        = u0[k];
        sU[(tt + 32) * HS_STRIDE + e0 + k] = u1[k];
    }

    float o20[8], o21[8];
#pragma unroll
    for (int k = 0; k < 8; k++) { o20[k] = b2[e0 + k]; o21[k] = o20[k]; }

    for (int jc = 0; jc < 4; jc++) {
        __syncthreads();
#pragma unroll
        for (int i = 0; i < 16; i++) {
            int idx = tid + i * 256;
            int d = idx >> 6, jj = idx & 63;
            sW1c[idx] = W1[d * 256 + jc * 64 + jj];
            sW2c[idx] = W2[(jc * 64 + (idx >> 6)) * 64 + (idx & 63)];
        }
        __syncthreads();
#pragma unroll
        for (int kk = 0; kk < 8; kk++) {
            int jl = eg + 8 * kk;
            float m0 = b1[jc * 64 + jl], m1 = m0;
#pragma unroll 8
            for (int d = 0; d < 64; d++) {
                float w = sW1c[d * 64 + jl];
                m0 = fmaf(sU[tt * HS_STRIDE + d], w, m0);
                m1 = fmaf(sU[(tt + 32) * HS_STRIDE + d], w, m1);
            }
            sGc[tt * HS_STRIDE + jl]        = 0.5f * m0 * (1.f + erff(m0 * 0.70710678118654752f));
            sGc[(tt + 32) * HS_STRIDE + jl] = 0.5f * m1 * (1.f + erff(m1 * 0.70710678118654752f));
        }
        __syncthreads();
#pragma unroll 8
        for (int jj = 0; jj < 64; jj++) {
            float gv0 = sGc[tt * HS_STRIDE + jj];
            float gv1 = sGc[(tt + 32) * HS_STRIDE + jj];
            float4 w0 = *(const float4*)&sW2c[jj * 64 + e0];
            float4 w1 = *(const float4*)&sW2c[jj * 64 + e0 + 4];
            o20[0] = fmaf(gv0, w0.x, o20[0]); o20[1] = fmaf(gv0, w0.y, o20[1]);
            o20[2] = fmaf(gv0, w0.z, o20[2]); o20[3] = fmaf(gv0, w0.w, o20[3]);
            o20[4] = fmaf(gv0, w1.x, o20[4]); o20[5] = fmaf(gv0, w1.y, o20[5]);
            o20[6] = fmaf(gv0, w1.z, o20[6]); o20[7] = fmaf(gv0, w1.w, o20[7]);
            o21[0] = fmaf(gv1, w0.x, o21[0]); o21[1] = fmaf(gv1, w0.y, o21[1]);
            o21[2] = fmaf(gv1, w0.z, o21[2]); o21[3] = fmaf(gv1, w0.w, o21[3]);
            o21[4] = fmaf(gv1, w1.x, o21[4]); o21[5] = fmaf(gv1, w1.y, o21[5]);
            o21[6] = fmaf(gv1, w1.z, o21[6]); o21[7] = fmaf(gv1, w1.w, o21[7]);
        }
    }

    __syncthreads();
#pragma unroll
    for (int k = 0; k < 8; k++) {
        sHo[tt * HS_STRIDE + e0 + k]        = u0[k] + o20[k];
        sHo[(tt + 32) * HS_STRIDE + e0 + k] = u1[k] + o21[k];
    }

    float fo0[8], fo1[8];
#pragma unroll
    for (int k = 0; k < 8; k++) { fo0[k] = bp[e0 + k]; fo1[k] = fo0[k]; }
    for (int dc = 0; dc < 2; dc++) {
        __syncthreads();
#pragma unroll
        for (int i = 0; i < 8; i++) {
            int idx = tid + i * 256;
            int d = idx >> 6, e = idx & 63;
            sW1c[idx] = Wp[(dc * 32 + d) * 64 + e];
        }
        __syncthreads();
#pragma unroll 8
        for (int d = 0; d < 32; d++) {
            float hv0 = sHo[tt * HS_STRIDE + dc * 32 + d];
            float hv1 = sHo[(tt + 32) * HS_STRIDE + dc * 32 + d];
            float4 w0 = *(const float4*)&sW1c[d * 64 + e0];
            float4 w1 = *(const float4*)&sW1c[d * 64 + e0 + 4];
            fo0[0] = fmaf(hv0, w0.x, fo0[0]); fo0[1] = fmaf(hv0, w0.y, fo0[1]);
            fo0[2] = fmaf(hv0, w0.z, fo0[2]); fo0[3] = fmaf(hv0, w0.w, fo0[3]);
            fo0[4] = fmaf(hv0, w1.x, fo0[4]); fo0[5] = fmaf(hv0, w1.y, fo0[5]);
            fo0[6] = fmaf(hv0, w1.z, fo0[6]); fo0[7] = fmaf(hv0, w1.w, fo0[7]);
            fo1[0] = fmaf(hv1, w0.x, fo1[0]); fo1[1] = fmaf(hv1, w0.y, fo1[1]);
            fo1[2] = fmaf(hv1, w0.z, fo1[2]); fo1[3] = fmaf(hv1, w0.w, fo1[3]);
            fo1[4] = fmaf(hv1, w1.x, fo1[4]); fo1[5] = fmaf(hv1, w1.y, fo1[5]);
            fo1[6] = fmaf(hv1, w1.z, fo1[6]); fo1[7] = fmaf(hv1, w1.w, fo1[7]);
        }
    }
#pragma unroll
    for (int k = 0; k < 8; k++) {
        out[tok0 * DH + e0 + k] = fo0[k];
        out[tok1 * DH + e0 + k] = fo1[k];
    }
}

// ---------------- launch ----------------
extern "C" void kernel_launch(void* const* d_in, const int* in_sizes, int n_in,
                              void* d_out, int out_size)
{
    const float* emb    = (const float*)d_in[0];
    const float* Wa     = (const float*)d_in[1];
    const float* ba     = (const float*)d_in[2];
    const float* Wb     = (const float*)d_in[3];
    const float* bb     = (const float*)d_in[4];
    const float* Wc     = (const float*)d_in[5];
    const float* bc     = (const float*)d_in[6];
    const float* head_w = (const float*)d_in[7];
    const float* hn_g   = (const float*)d_in[8];
    const float* hn_b   = (const float*)d_in[9];
    const float* Wd     = (const float*)d_in[10];
    const float* bd     = (const float*)d_in[11];
    const float* W1     = (const float*)d_in[12];
    const float* b1     = (const float*)d_in[13];
    const float* W2     = (const float*)d_in[14];
    const float* b2     = (const float*)d_in[15];
    const float* Wp     = (const float*)d_in[16];
    const float* bp     = (const float*)d_in[17];
    const float* ng     = (const float*)d_in[18];
    const float* nb     = (const float*)d_in[19];
    float* out = (float*)d_out;

    cudaFuncSetAttribute(gemm_tf32_kernel, cudaFuncAttributeMaxDynamicSharedMemorySize, GEMM_SMEM);
    cudaFuncSetAttribute(post_kernel, cudaFuncAttributeMaxDynamicSharedMemorySize, POST_BYTES);

    preround_kernel<<<(int)((size_t)MT * GK / 4 / 256), 256>>>(emb);
    pack_a_kernel<<<4096, 256>>>(Wa);
    pack_bd_kernel<<<4608, 256>>>(Wb, Wd);

    dim3 ggrid(GNP / 128, MT / 128);
    gemm_tf32_kernel<<<ggrid, 256, GEMM_SMEM>>>(ba, bb, bd);

    scanA_kernel<<<BB * SCH, 1024>>>();
    scanC_kernel<<<BB * SCH, 1024>>>();

    post_kernel<<<MT / TOK, 256, POST_BYTES>>>(Wc, bc, head_w, hn_g, hn_b,
                                               W1, b1, W2, b2, Wp, bp, ng, nb, out);
}

// round 14
// speedup vs baseline: 1.1188x; 1.0174x over previous
#include <cuda_runtime.h>
#include <cuda_bf16.h>
#include <math.h>
#include <stdint.h>

// Problem constants
#define EB 1024     // embed dim
#define DH 64       // head dim
#define NH 16       // heads
#define BB 8
#define LL 4096
#define MT (BB*LL)          // 32768 tokens
#define GNP 2176            // padded N (17 tiles of 128)
#define GK EB

// ---------------- scratch ----------------
__device__ float g_a [ (size_t)MT * EB ];
__device__ float g_b [ (size_t)MT * EB ];
__device__ float g_hs[ (size_t)MT * EB ];
__device__ float g_dx[ (size_t)MT * DH ];
__device__ float g_wt[ (size_t)GNP * GK ];  // weights [n][k], tf32-rounded
__device__ float g_et[ (size_t)MT * GK ];   // emb, tf32-rounded

#define SCH 64
#define SCL (LL / SCH)      // 64
__device__ float g_cp[128 * SCH * 64];
__device__ float g_cq[128 * SCH * 64];

// ---------------- helpers ----------------
__device__ __forceinline__ uint32_t smem_u32(const void* p) {
    uint32_t r;
    asm("{ .reg .u64 t; cvta.to.shared.u64 t, %1; cvt.u32.u64 %0, t; }" : "=r"(r) : "l"(p));
    return r;
}
__device__ __forceinline__ void cp_async16(uint32_t dst, const void* src) {
    asm volatile("cp.async.cg.shared.global [%0], [%1], 16;" :: "r"(dst), "l"(src) : "memory");
}
__device__ __forceinline__ void cp_commit() {
    asm volatile("cp.async.commit_group;" ::: "memory");
}
__device__ __forceinline__ uint32_t tf32u(float x) {
    uint32_t u;
    asm("cvt.rna.tf32.f32 %0, %1;" : "=r"(u) : "f"(x));
    return u;
}
__device__ __forceinline__ void mma_tf32(float* c,
                                         uint32_t a0, uint32_t a1, uint32_t a2, uint32_t a3,
                                         uint32_t b0, uint32_t b1) {
    asm volatile(
        "mma.sync.aligned.m16n8k8.row.col.f32.tf32.tf32.f32 "
        "{%0,%1,%2,%3}, {%4,%5,%6,%7}, {%8,%9}, {%0,%1,%2,%3};"
        : "+f"(c[0]), "+f"(c[1]), "+f"(c[2]), "+f"(c[3])
        : "r"(a0), "r"(a1), "r"(a2), "r"(a3), "r"(b0), "r"(b1));
}
__device__ __forceinline__ float tanh_fast(float x) {
    float xc = fminf(fmaxf(x, -10.f), 10.f);
    float t  = __expf(2.f * xc);
    return __fdividef(t - 1.f, t + 1.f);
}

// ---------------- launch 0: pre-round emb to tf32 ----------------
__global__ void preround_kernel(const float* __restrict__ emb)
{
    size_t i = ((size_t)blockIdx.x * 256 + threadIdx.x) * 4;
    float4 x = *(const float4*)(emb + i);
    float4 y;
    y.x = __uint_as_float(tf32u(x.x));
    y.y = __uint_as_float(tf32u(x.y));
    y.z = __uint_as_float(tf32u(x.z));
    y.w = __uint_as_float(tf32u(x.w));
    *(float4*)(g_et + i) = y;
}

// ---------------- launches 1,2: pack weights [n][k] ----------------
__global__ void pack_a_kernel(const float* __restrict__ Wa)
{
    size_t idx = (size_t)blockIdx.x * 256 + threadIdx.x;
    int n = (int)(idx >> 10);
    int k = (int)(idx & 1023);
    float v = Wa[(size_t)(n >> 6) * (EB * DH) + (size_t)k * DH + (n & 63)];
    g_wt[idx] = __uint_as_float(tf32u(v));
}
__global__ void pack_bd_kernel(const float* __restrict__ Wb, const float* __restrict__ Wd)
{
    size_t idx = (size_t)blockIdx.x * 256 + threadIdx.x;
    int n = (int)(idx >> 10);
    int k = (int)(idx & 1023);
    float v;
    if (n < 1024) {
        v = Wb[(size_t)(n >> 6) * (EB * DH) + (size_t)k * DH + (n & 63)];
    } else {
        int n2 = n - 1024;
        v = (n2 < 64) ? Wd[(size_t)k * DH + n2] : 0.f;
    }
    g_wt[(size_t)(1024 + n) * 1024 + k] = __uint_as_float(tf32u(v));
}

// ---------------- launch 3: TF32 gates GEMM, CTA 128x128, warp 32x64 ----------------
#define KC 32
#define NKC (GK / KC)          // 32
#define ROWB 128
#define TILEB (128 * ROWB)     // 16384
#define STAGEB (2 * TILEB)     // A + B = 32768
#define GEMM_SMEM (3 * STAGEB) // 98304 (>= epilogue sD 67584)

#define SWZ(row, chunk) ((uint32_t)((row) * ROWB + ((((chunk) ^ (((row) & 1) << 2))) << 4)))

__device__ __forceinline__ void gemm_load_stage(uint32_t sst, int kc, int tid,
                                                const char* Ag, const char* Bg)
{
    const size_t kb = (size_t)kc * 128;
#pragma unroll
    for (int j = 0; j < 4; j++) {
        int id  = tid + j * 256;
        int row = id >> 3;
        int c   = id & 7;
        cp_async16(sst + SWZ(row, c),         Ag + (size_t)row * 4096 + kb + c * 16);
        cp_async16(sst + TILEB + SWZ(row, c), Bg + (size_t)row * 4096 + kb + c * 16);
    }
}

__global__ void __launch_bounds__(256, 2)
gemm_tf32_kernel(const float* __restrict__ ba,
                 const float* __restrict__ bb,
                 const float* __restrict__ bd)
{
    extern __shared__ char sm_raw[];
    const int tid  = threadIdx.x;
    const int wid  = tid >> 5;
    const int lane = tid & 31;
    const uint32_t sbase = smem_u32(sm_raw);

    const long m0 = (long)blockIdx.y * 128;
    const int  n0 = blockIdx.x * 128;
    const int  wm = (wid & 3) * 32;
    const int  wn = (wid >> 2) * 64;

    const char* Ag = (const char*)(g_et + (size_t)m0 * GK);
    const char* Bg = (const char*)(g_wt + (size_t)n0 * GK);

    float acc[2][8][4];
#pragma unroll
    for (int i = 0; i < 2; i++)
#pragma unroll
        for (int j = 0; j < 8; j++)
#pragma unroll
            for (int q = 0; q < 4; q++) acc[i][j][q] = 0.f;

    gemm_load_stage(sbase, 0, tid, Ag, Bg);
    cp_commit();
    gemm_load_stage(sbase + STAGEB, 1, tid, Ag, Bg);
    cp_commit();

    const int lrow4 = lane >> 2;
    const int lch   = lane & 3;

    int stage = 0;
#pragma unroll 3
    for (int kc = 0; kc < NKC; kc++) {
        if (kc + 1 < NKC) {
            asm volatile("cp.async.wait_group 1;" ::: "memory");
        } else {
            asm volatile("cp.async.wait_group 0;" ::: "memory");
        }
        __syncthreads();
        if (kc + 2 < NKC) {
            int nstage = stage + 2; if (nstage >= 3) nstage -= 3;
            gemm_load_stage(sbase + nstage * STAGEB, kc + 2, tid, Ag, Bg);
            cp_commit();
        }

        const char* sA = sm_raw + stage * STAGEB;
        const char* sB = sA + TILEB;

#pragma unroll
        for (int k16 = 0; k16 < 2; k16++) {
            const int ch = k16 * 4 + lch;
            uint32_t aw[2][2][4];
#pragma unroll
            for (int mt = 0; mt < 2; mt++) {
#pragma unroll
                for (int hh = 0; hh < 2; hh++) {
                    int row = wm + mt * 16 + hh * 8 + lrow4;
                    const uint4 v = *(const uint4*)(sA + SWZ(row, ch));
                    aw[mt][hh][0] = v.x;
                    aw[mt][hh][1] = v.y;
                    aw[mt][hh][2] = v.z;
                    aw[mt][hh][3] = v.w;
                }
            }
#pragma unroll
            for (int g = 0; g < 8; g++) {
                int row = wn + g * 8 + lrow4;
                const uint4 bv = *(const uint4*)(sB + SWZ(row, ch));
                mma_tf32(acc[0][g], aw[0][0][0], aw[0][1][0], aw[0][0][1], aw[0][1][1], bv.x, bv.y);
                mma_tf32(acc[0][g], aw[0][0][2], aw[0][1][2], aw[0][0][3], aw[0][1][3], bv.z, bv.w);
                mma_tf32(acc[1][g], aw[1][0][0], aw[1][1][0], aw[1][0][1], aw[1][1][1], bv.x, bv.y);
                mma_tf32(acc[1][g], aw[1][0][2], aw[1][1][2], aw[1][0][3], aw[1][1][3], bv.z, bv.w);
            }
        }
        stage++; if (stage == 3) stage = 0;
    }
    __syncthreads();

    // ---- epilogue ----
    float* sD = (float*)sm_raw;   // 128 x 132
#pragma unroll
    for (int mt = 0; mt < 2; mt++) {
#pragma unroll
        for (int g = 0; g < 8; g++) {
            int ml = wm + mt * 16 + (lane >> 2);
            int nl = wn + g * 8 + (lane & 3) * 2;
            *(float2*)&sD[ml * 132 + nl]       = make_float2(acc[mt][g][0], acc[mt][g][1]);
            *(float2*)&sD[(ml + 8) * 132 + nl] = make_float2(acc[mt][g][2], acc[mt][g][3]);
        }
    }
    __syncthreads();

    for (int i = tid; i < 128 * 128; i += 256) {
        int mm = i >> 7;
        int nn = i & 127;
        int ng = n0 + nn;
        float c = sD[mm * 132 + nn];
        long m = m0 + mm;
        if (ng < 1024) {
            __stcs(&g_a[m * EB + ng], tanh_fast(c + ba[ng]));
        } else if (ng < 2048) {
            __stcs(&g_b[m * EB + (ng - 1024)], c + bb[ng - 1024]);
        } else if (ng < 2112) {
            __stcs(&g_dx[m * DH + (ng - 2048)], c + bd[ng - 2048]);
        }
    }
}

// ---------------- chunked scan: SCH=64, float2 per thread ----------------
__global__ void __launch_bounds__(512)
scanA_kernel()
{
    const int b = blockIdx.x >> 6;        // batch
    const int c = blockIdx.x & 63;        // chunk
    const int e2 = threadIdx.x;           // dim pair 0..511
    size_t base = ((size_t)b * LL + (size_t)c * SCL) * EB + 2 * e2;
    float2 P = make_float2(1.f, 1.f), Q = make_float2(0.f, 0.f);
#pragma unroll 8
    for (int l = 0; l < SCL; l++) {
        size_t idx = base + (size_t)l * EB;
        float2 av = __ldcs((const float2*)(g_a + idx));
        float2 bv = __ldcs((const float2*)(g_b + idx));
        Q.x = fmaf(av.x, Q.x, bv.x);
        Q.y = fmaf(av.y, Q.y, bv.y);
        P.x *= av.x;
        P.y *= av.y;
    }
    const int bh = b * 16 + (e2 >> 5);      // head = (2*e2)/64
    const int d  = (2 * e2) & 63;
    *(float2*)(g_cp + ((size_t)(bh * SCH + c) * 64 + d)) = P;
    *(float2*)(g_cq + ((size_t)(bh * SCH + c) * 64 + d)) = Q;
}

__global__ void __launch_bounds__(512)
scanC_kernel()
{
    const int b = blockIdx.x >> 6;
    const int c = blockIdx.x & 63;
    const int e2 = threadIdx.x;
    const int bh = b * 16 + (e2 >> 5);
    const int d  = (2 * e2) & 63;
    float2 hv = make_float2(0.f, 0.f);
    for (int cc = 0; cc < c; cc++) {
        size_t i = (size_t)(bh * SCH + cc) * 64 + d;
        float2 cp = *(const float2*)(g_cp + i);
        float2 cq = *(const float2*)(g_cq + i);
        hv.x = fmaf(cp.x, hv.x, cq.x);
        hv.y = fmaf(cp.y, hv.y, cq.y);
    }
    size_t base = ((size_t)b * LL + (size_t)c * SCL) * EB + 2 * e2;
#pragma unroll 8
    for (int l = 0; l < SCL; l++) {
        size_t idx = base + (size_t)l * EB;
        float2 av = __ldcs((const float2*)(g_a + idx));
        float2 bv = __ldcs((const float2*)(g_b + idx));
        hv.x = fmaf(av.x, hv.x, bv.x);
        hv.y = fmaf(av.y, hv.y, bv.y);
        __stcs((float2*)(g_hs + idx), hv);
    }
}

// ---------------- fused per-token epilogue ----------------
#define TOK 64
#define HS_STRIDE 68
#define POST_FLOATS 21248
#define POST_BYTES  (POST_FLOATS * 4)

__device__ __forceinline__ float grp8_sum(float v) {
    v += __shfl_xor_sync(0xffffffffu, v, 1);
    v += __shfl_xor_sync(0xffffffffu, v, 2);
    v += __shfl_xor_sync(0xffffffffu, v, 4);
    return v;
}

__device__ __forceinline__ void post_prefetch(uint32_t swc, uint32_t shs,
                                              const float* __restrict__ Wc,
                                              int h, long token0, int tid)
{
    const char* wsrc = (const char*)(Wc + (size_t)h * 4096);
#pragma unroll
    for (int i = 0; i < 4; i++) {
        int idx = tid + i * 256;
        cp_async16(swc + idx * 16, wsrc + idx * 16);
    }
#pragma unroll
    for (int i = 0; i < 4; i++) {
        int idx = tid + i * 256;
        int t = idx >> 4;
        int c = idx & 15;
        const char* hsrc = (const char*)(g_hs + (token0 + t) * (size_t)EB + h * 64);
        cp_async16(shs + (uint32_t)(t * HS_STRIDE * 4 + c * 16), hsrc + c * 16);
    }
}

__global__ void __launch_bounds__(256)
post_kernel(const float* __restrict__ Wc,  const float* __restrict__ bc,
            const float* __restrict__ head_w,
            const float* __restrict__ hn_g, const float* __restrict__ hn_b,
            const float* __restrict__ W1,  const float* __restrict__ b1,
            const float* __restrict__ W2,  const float* __restrict__ b2,
            const float* __restrict__ Wp,  const float* __restrict__ bp,
            const float* __restrict__ ng,  const float* __restrict__ nb,
            float* __restrict__ out)
{
    extern __shared__ float sm[];
    const int tid = threadIdx.x;
    const int tt  = tid >> 3;
    const int eg  = tid & 7;
    const int e0  = eg * 8;
    const long token0 = (long)blockIdx.x * TOK;
    const long tok0 = token0 + tt;
    const long tok1 = token0 + tt + 32;

    const uint32_t swc_u0 = smem_u32(sm);
    const uint32_t swc_u1 = smem_u32(sm + 4096);
    const uint32_t shs_u0 = smem_u32(sm + 8192);
    const uint32_t shs_u1 = smem_u32(sm + 8192 + TOK * HS_STRIDE);

    float dxv0[8], dxv1[8], acc0[8], acc1[8];
#pragma unroll
    for (int k = 0; k < 8; k++) {
        dxv0[k] = g_dx[tok0 * DH + e0 + k];
        dxv1[k] = g_dx[tok1 * DH + e0 + k];
        acc0[k] = dxv0[k];
        acc1[k] = dxv1[k];
    }

    post_prefetch(swc_u0, shs_u0, Wc, 0, token0, tid);
    cp_commit();

    for (int h = 0; h < NH; h++) {
        const int cur = h & 1;
        if (h + 1 < NH) {
            post_prefetch(cur ? swc_u0 : swc_u1, cur ? shs_u0 : shs_u1, Wc, h + 1, token0, tid);
            cp_commit();
            asm volatile("cp.async.wait_group 1;" ::: "memory");
        } else {
            asm volatile("cp.async.wait_group 0;" ::: "memory");
        }
        __syncthreads();

        const float* sWc = sm + (cur ? 4096 : 0);
        const float* sHs = sm + 8192 + (cur ? TOK * HS_STRIDE : 0);

        float o0[8], o1[8];
#pragma unroll
        for (int k = 0; k < 8; k++) {
            float bck = bc[h * DH + e0 + k];
            o0[k] = bck + dxv0[k];
            o1[k] = bck + dxv1[k];
        }
#pragma unroll 8
        for (int d = 0; d < 64; d++) {
            float hv0 = sHs[tt * HS_STRIDE + d];
            float hv1 = sHs[(tt + 32) * HS_STRIDE + d];
            float4 w0 = *(const float4*)&sWc[d * 64 + e0];
            float4 w1 = *(const float4*)&sWc[d * 64 + e0 + 4];
            o0[0] = fmaf(hv0, w0.x, o0[0]); o0[1] = fmaf(hv0, w0.y, o0[1]);
            o0[2] = fmaf(hv0, w0.z, o0[2]); o0[3] = fmaf(hv0, w0.w, o0[3]);
            o0[4] = fmaf(hv0, w1.x, o0[4]); o0[5] = fmaf(hv0, w1.y, o0[5]);
            o0[6] = fmaf(hv0, w1.z, o0[6]); o0[7] = fmaf(hv0, w1.w, o0[7]);
            o1[0] = fmaf(hv1, w0.x, o1[0]); o1[1] = fmaf(hv1, w0.y, o1[1]);
            o1[2] = fmaf(hv1, w0.z, o1[2]); o1[3] = fmaf(hv1, w0.w, o1[3]);
            o1[4] = fmaf(hv1, w1.x, o1[4]); o1[5] = fmaf(hv1, w1.y, o1[5]);
            o1[6] = fmaf(hv1, w1.z, o1[6]); o1[7] = fmaf(hv1, w1.w, o1[7]);
        }
        float s10 = 0.f, s20 = 0.f, s11 = 0.f, s21 = 0.f;
#pragma unroll
        for (int k = 0; k < 8; k++) {
            s10 += o0[k]; s20 += o0[k] * o0[k];
            s11 += o1[k]; s21 += o1[k] * o1[k];
        }
        s10 = grp8_sum(s10); s20 = grp8_sum(s20);
        s11 = grp8_sum(s11); s21 = grp8_sum(s21);
        float mean0 = s10 * (1.f / 64.f);
        float var0  = s20 * (1.f / 64.f) - mean0 * mean0;
        float rstd0 = rsqrtf(var0 + 1e-5f);
        float mean1 = s11 * (1.f / 64.f);
        float var1  = s21 * (1.f / 64.f) - mean1 * mean1;
        float rstd1 = rsqrtf(var1 + 1e-5f);
        float hw = head_w[h];
#pragma unroll
        for (int k = 0; k < 8; k++) {
            float gk = hn_g[h * DH + e0 + k];
            float bk = hn_b[h * DH + e0 + k];
            acc0[k] = fmaf(hw, (o0[k] - mean0) * rstd0 * gk + bk, acc0[k]);
            acc1[k] = fmaf(hw, (o1[k] - mean1) * rstd1 * gk + bk, acc1[k]);
        }
        __syncthreads();
    }

    float u0[8], u1[8];
    {
        float s10 = 0.f, s20 = 0.f, s11 = 0.f, s21 = 0.f;
#pragma unroll
        for (int k = 0; k < 8; k++) {
            acc0[k] *= (1.f / (float)NH);
            acc1[k] *= (1.f / (float)NH);
            s10 += acc0[k]; s20 += acc0[k] * acc0[k];
            s11 += acc1[k]; s21 += acc1[k] * acc1[k];
        }
        s10 = grp8_sum(s10); s20 = grp8_sum(s20);
        s11 = grp8_sum(s11); s21 = grp8_sum(s21);
        float mean0 = s10 * (1.f / 64.f);
        float var0  = s20 * (1.f / 64.f) - mean0 * mean0;
        float rstd0 = rsqrtf(var0 + 1e-5f);
        float mean1 = s11 * (1.f / 64.f);
        float var1  = s21 * (1.f / 64.f) - mean1 * mean1;
        float rstd1 = rsqrtf(var1 + 1e-5f);
#pragma unroll
        for (int k = 0; k < 8; k++) {
            float ngk = ng[e0 + k], nbk = nb[e0 + k];
            u0[k] = acc0[k] + (acc0[k] - mean0) * rstd0 * ngk + nbk;
            u1[k] = acc1[k] + (acc1[k] - mean1) * rstd1 * ngk + nbk;
        }
    }

    __syncthreads();

    float* sW1c = sm;
    float* sW2c = sm + 4096;
    float* sU   = sm + 8192;
    float* sGc  = sm + 8192 + TOK * HS_STRIDE;
    float* sHo  = sm + 8192 + 2 * TOK * HS_STRIDE;

#pragma unroll
    for (int k = 0; k < 8; k++) {
        sU[tt * HS_STRIDE + e0 + k]        = u0[k];
        sU[(tt + 32) * HS_STRIDE + e0 + k] = u1[k];
    }

    float o20[8], o21[8];
#pragma unroll
    for (int k = 0; k < 8; k++) { o20[k] = b2[e0 + k]; o21[k] = o20[k]; }

    for (int jc = 0; jc < 4; jc++) {
        __syncthreads();
#pragma unroll
        for (int i = 0; i < 16; i++) {
            int idx = tid + i * 256;
            int d = idx >> 6, jj = idx & 63;
            sW1c[idx] = W1[d * 256 + jc * 64 + jj];
            sW2c[idx] = W2[(jc * 64 + (idx >> 6)) * 64 + (idx & 63)];
        }
        __syncthreads();
#pragma unroll
        for (int kk = 0; kk < 8; kk++) {
            int jl = eg + 8 * kk;
            float m0 = b1[jc * 64 + jl], m1 = m0;
#pragma unroll 8
            for (int d = 0; d < 64; d++) {
                float w = sW1c[d * 64 + jl];
                m0 = fmaf(sU[tt * HS_STRIDE + d], w, m0);
                m1 = fmaf(sU[(tt + 32) * HS_STRIDE + d], w, m1);
            }
            sGc[tt * HS_STRIDE + jl]        = 0.5f * m0 * (1.f + erff(m0 * 0.70710678118654752f));
            sGc[(tt + 32) * HS_STRIDE + jl] = 0.5f * m1 * (1.f + erff(m1 * 0.70710678118654752f));
        }
        __syncthreads();
#pragma unroll 8
        for (int jj = 0; jj < 64; jj++) {
            float gv0 = sGc[tt * HS_STRIDE + jj];
            float gv1 = sGc[(tt + 32) * HS_STRIDE + jj];
            float4 w0 = *(const float4*)&sW2c[jj * 64 + e0];
            float4 w1 = *(const float4*)&sW2c[jj * 64 + e0 + 4];
            o20[0] = fmaf(gv0, w0.x, o20[0]); o20[1] = fmaf(gv0, w0.y, o20[1]);
            o20[2] = fmaf(gv0, w0.z, o20[2]); o20[3] = fmaf(gv0, w0.w, o20[3]);
            o20[4] = fmaf(gv0, w1.x, o20[4]); o20[5] = fmaf(gv0, w1.y, o20[5]);
            o20[6] = fmaf(gv0, w1.z, o20[6]); o20[7] = fmaf(gv0, w1.w, o20[7]);
            o21[0] = fmaf(gv1, w0.x, o21[0]); o21[1] = fmaf(gv1, w0.y, o21[1]);
            o21[2] = fmaf(gv1, w0.z, o21[2]); o21[3] = fmaf(gv1, w0.w, o21[3]);
            o21[4] = fmaf(gv1, w1.x, o21[4]); o21[5] = fmaf(gv1, w1.y, o21[5]);
            o21[6] = fmaf(gv1, w1.z, o21[6]); o21[7] = fmaf(gv1, w1.w, o21[7]);
        }
    }

    __syncthreads();
#pragma unroll
    for (int k = 0; k < 8; k++) {
        sHo[tt * HS_STRIDE + e0 + k]        = u0[k] + o20[k];
        sHo[(tt + 32) * HS_STRIDE + e0 + k] = u1[k] + o21[k];
    }

    float fo0[8], fo1[8];
#pragma unroll
    for (int k = 0; k < 8; k++) { fo0[k] = bp[e0 + k]; fo1[k] = fo0[k]; }
    for (int dc = 0; dc < 2; dc++) {
        __syncthreads();
#pragma unroll
        for (int i = 0; i < 8; i++) {
            int idx = tid + i * 256;
            int d = idx >> 6, e = idx & 63;
            sW1c[idx] = Wp[(dc * 32 + d) * 64 + e];
        }
        __syncthreads();
#pragma unroll 8
        for (int d = 0; d < 32; d++) {
            float hv0 = sHo[tt * HS_STRIDE + dc * 32 + d];
            float hv1 = sHo[(tt + 32) * HS_STRIDE + dc * 32 + d];
            float4 w0 = *(const float4*)&sW1c[d * 64 + e0];
            float4 w1 = *(const float4*)&sW1c[d * 64 + e0 + 4];
            fo0[0] = fmaf(hv0, w0.x, fo0[0]); fo0[1] = fmaf(hv0, w0.y, fo0[1]);
            fo0[2] = fmaf(hv0, w0.z, fo0[2]); fo0[3] = fmaf(hv0, w0.w, fo0[3]);
            fo0[4] = fmaf(hv0, w1.x, fo0[4]); fo0[5] = fmaf(hv0, w1.y, fo0[5]);
            fo0[6] = fmaf(hv0, w1.z, fo0[6]); fo0[7] = fmaf(hv0, w1.w, fo0[7]);
            fo1[0] = fmaf(hv1, w0.x, fo1[0]); fo1[1] = fmaf(hv1, w0.y, fo1[1]);
            fo1[2] = fmaf(hv1, w0.z, fo1[2]); fo1[3] = fmaf(hv1, w0.w, fo1[3]);
            fo1[4] = fmaf(hv1, w1.x, fo1[4]); fo1[5] = fmaf(hv1, w1.y, fo1[5]);
            fo1[6] = fmaf(hv1, w1.z, fo1[6]); fo1[7] = fmaf(hv1, w1.w, fo1[7]);
        }
    }
#pragma unroll
    for (int k = 0; k < 8; k++) {
        out[tok0 * DH + e0 + k] = fo0[k];
        out[tok1 * DH + e0 + k] = fo1[k];
    }
}

// ---------------- launch ----------------
extern "C" void kernel_launch(void* const* d_in, const int* in_sizes, int n_in,
                              void* d_out, int out_size)
{
    const float* emb    = (const float*)d_in[0];
    const float* Wa     = (const float*)d_in[1];
    const float* ba     = (const float*)d_in[2];
    const float* Wb     = (const float*)d_in[3];
    const float* bb     = (const float*)d_in[4];
    const float* Wc     = (const float*)d_in[5];
    const float* bc     = (const float*)d_in[6];
    const float* head_w = (const float*)d_in[7];
    const float* hn_g   = (const float*)d_in[8];
    const float* hn_b   = (const float*)d_in[9];
    const float* Wd     = (const float*)d_in[10];
    const float* bd     = (const float*)d_in[11];
    const float* W1     = (const float*)d_in[12];
    const float* b1     = (const float*)d_in[13];
    const float* W2     = (const float*)d_in[14];
    const float* b2     = (const float*)d_in[15];
    const float* Wp     = (const float*)d_in[16];
    const float* bp     = (const float*)d_in[17];
    const float* ng     = (const float*)d_in[18];
    const float* nb     = (const float*)d_in[19];
    float* out = (float*)d_out;

    cudaFuncSetAttribute(gemm_tf32_kernel, cudaFuncAttributeMaxDynamicSharedMemorySize, GEMM_SMEM);
    cudaFuncSetAttribute(post_kernel, cudaFuncAttributeMaxDynamicSharedMemorySize, POST_BYTES);

    preround_kernel<<<(int)((size_t)MT * GK / 4 / 256), 256>>>(emb);
    pack_a_kernel<<<4096, 256>>>(Wa);
    pack_bd_kernel<<<4608, 256>>>(Wb, Wd);

    dim3 ggrid(GNP / 128, MT / 128);
    gemm_tf32_kernel<<<ggrid, 256, GEMM_SMEM>>>(ba, bb, bd);

    scanA_kernel<<<BB * SCH, 512>>>();
    scanC_kernel<<<BB * SCH, 512>>>();

    post_kernel<<<MT / TOK, 256, POST_BYTES>>>(Wc, bc, head_w, hn_g, hn_b,
                                               W1, b1, W2, b2, Wp, bp, ng, nb, out);
}

// round 15
// speedup vs baseline: 1.2767x; 1.1411x over previous
#include <cuda_runtime.h>
#include <cuda_bf16.h>
#include <math.h>
#include <stdint.h>

// Problem constants
#define EB 1024     // embed dim
#define DH 64       // head dim
#define NH 16       // heads
#define BB 8
#define LL 4096
#define MT (BB*LL)          // 32768 tokens
#define GNP 2176            // padded N (17 tiles of 128)
#define GK EB

// ---------------- scratch ----------------
__device__ float g_a [ (size_t)MT * EB ];
__device__ float g_b [ (size_t)MT * EB ];
__device__ float g_hs[ (size_t)MT * EB ];   // scan out, tf32-rounded at store
__device__ float g_o [ (size_t)MT * EB ];   // per-head o = hs@Wc + bc + dx
__device__ float g_dx[ (size_t)MT * DH ];
__device__ float g_wt[ (size_t)GNP * GK ];  // gates weights [n][k], tf32
__device__ float g_et[ (size_t)MT * GK ];   // emb, tf32
__device__ float g_wc2[ NH * DH * DH ];     // Wc^T per head [h][e][d], tf32

#define SCH 64
#define SCL (LL / SCH)      // 64
__device__ float g_cp[128 * SCH * 64];
__device__ float g_cq[128 * SCH * 64];

// ---------------- helpers ----------------
__device__ __forceinline__ uint32_t smem_u32(const void* p) {
    uint32_t r;
    asm("{ .reg .u64 t; cvta.to.shared.u64 t, %1; cvt.u32.u64 %0, t; }" : "=r"(r) : "l"(p));
    return r;
}
__device__ __forceinline__ void cp_async16(uint32_t dst, const void* src) {
    asm volatile("cp.async.cg.shared.global [%0], [%1], 16;" :: "r"(dst), "l"(src) : "memory");
}
__device__ __forceinline__ void cp_commit() {
    asm volatile("cp.async.commit_group;" ::: "memory");
}
__device__ __forceinline__ uint32_t tf32u(float x) {
    uint32_t u;
    asm("cvt.rna.tf32.f32 %0, %1;" : "=r"(u) : "f"(x));
    return u;
}
__device__ __forceinline__ void mma_tf32(float* c,
                                         uint32_t a0, uint32_t a1, uint32_t a2, uint32_t a3,
                                         uint32_t b0, uint32_t b1) {
    asm volatile(
        "mma.sync.aligned.m16n8k8.row.col.f32.tf32.tf32.f32 "
        "{%0,%1,%2,%3}, {%4,%5,%6,%7}, {%8,%9}, {%0,%1,%2,%3};"
        : "+f"(c[0]), "+f"(c[1]), "+f"(c[2]), "+f"(c[3])
        : "r"(a0), "r"(a1), "r"(a2), "r"(a3), "r"(b0), "r"(b1));
}
__device__ __forceinline__ float tanh_fast(float x) {
    float xc = fminf(fmaxf(x, -10.f), 10.f);
    float t  = __expf(2.f * xc);
    return __fdividef(t - 1.f, t + 1.f);
}

// ---------------- launch 0: pre-round emb to tf32 ----------------
__global__ void preround_kernel(const float* __restrict__ emb)
{
    size_t i = ((size_t)blockIdx.x * 256 + threadIdx.x) * 4;
    float4 x = *(const float4*)(emb + i);
    float4 y;
    y.x = __uint_as_float(tf32u(x.x));
    y.y = __uint_as_float(tf32u(x.y));
    y.z = __uint_as_float(tf32u(x.z));
    y.w = __uint_as_float(tf32u(x.w));
    *(float4*)(g_et + i) = y;
}

// ---------------- launches 1,2: pack gates weights [n][k] ----------------
__global__ void pack_a_kernel(const float* __restrict__ Wa)
{
    size_t idx = (size_t)blockIdx.x * 256 + threadIdx.x;
    int n = (int)(idx >> 10);
    int k = (int)(idx & 1023);
    float v = Wa[(size_t)(n >> 6) * (EB * DH) + (size_t)k * DH + (n & 63)];
    g_wt[idx] = __uint_as_float(tf32u(v));
}
__global__ void pack_bd_kernel(const float* __restrict__ Wb, const float* __restrict__ Wd)
{
    size_t idx = (size_t)blockIdx.x * 256 + threadIdx.x;
    int n = (int)(idx >> 10);
    int k = (int)(idx & 1023);
    float v;
    if (n < 1024) {
        v = Wb[(size_t)(n >> 6) * (EB * DH) + (size_t)k * DH + (n & 63)];
    } else {
        int n2 = n - 1024;
        v = (n2 < 64) ? Wd[(size_t)k * DH + n2] : 0.f;
    }
    g_wt[(size_t)(1024 + n) * 1024 + k] = __uint_as_float(tf32u(v));
}

// ---------------- launch 3: TF32 gates GEMM (R13/R14 config, unchanged) ----------------
#define KC 32
#define NKC (GK / KC)          // 32
#define ROWB 128
#define TILEB (128 * ROWB)     // 16384
#define STAGEB (2 * TILEB)     // A + B = 32768
#define GEMM_SMEM (3 * STAGEB) // 98304

#define SWZ(row, chunk) ((uint32_t)((row) * ROWB + ((((chunk) ^ (((row) & 1) << 2))) << 4)))

__device__ __forceinline__ void gemm_load_stage(uint32_t sst, int kc, int tid,
                                                const char* Ag, const char* Bg)
{
    const size_t kb = (size_t)kc * 128;
#pragma unroll
    for (int j = 0; j < 4; j++) {
        int id  = tid + j * 256;
        int row = id >> 3;
        int c   = id & 7;
        cp_async16(sst + SWZ(row, c),         Ag + (size_t)row * 4096 + kb + c * 16);
        cp_async16(sst + TILEB + SWZ(row, c), Bg + (size_t)row * 4096 + kb + c * 16);
    }
}

__global__ void __launch_bounds__(256, 2)
gemm_tf32_kernel(const float* __restrict__ ba,
                 const float* __restrict__ bb,
                 const float* __restrict__ bd)
{
    extern __shared__ char sm_raw[];
    const int tid  = threadIdx.x;
    const int wid  = tid >> 5;
    const int lane = tid & 31;
    const uint32_t sbase = smem_u32(sm_raw);

    const long m0 = (long)blockIdx.y * 128;
    const int  n0 = blockIdx.x * 128;
    const int  wm = (wid & 3) * 32;
    const int  wn = (wid >> 2) * 64;

    const char* Ag = (const char*)(g_et + (size_t)m0 * GK);
    const char* Bg = (const char*)(g_wt + (size_t)n0 * GK);

    float acc[2][8][4];
#pragma unroll
    for (int i = 0; i < 2; i++)
#pragma unroll
        for (int j = 0; j < 8; j++)
#pragma unroll
            for (int q = 0; q < 4; q++) acc[i][j][q] = 0.f;

    gemm_load_stage(sbase, 0, tid, Ag, Bg);
    cp_commit();
    gemm_load_stage(sbase + STAGEB, 1, tid, Ag, Bg);
    cp_commit();

    const int lrow4 = lane >> 2;
    const int lch   = lane & 3;

    int stage = 0;
#pragma unroll 3
    for (int kc = 0; kc < NKC; kc++) {
        if (kc + 1 < NKC) {
            asm volatile("cp.async.wait_group 1;" ::: "memory");
        } else {
            asm volatile("cp.async.wait_group 0;" ::: "memory");
        }
        __syncthreads();
        if (kc + 2 < NKC) {
            int nstage = stage + 2; if (nstage >= 3) nstage -= 3;
            gemm_load_stage(sbase + nstage * STAGEB, kc + 2, tid, Ag, Bg);
            cp_commit();
        }

        const char* sA = sm_raw + stage * STAGEB;
        const char* sB = sA + TILEB;

#pragma unroll
        for (int k16 = 0; k16 < 2; k16++) {
            const int ch = k16 * 4 + lch;
            uint32_t aw[2][2][4];
#pragma unroll
            for (int mt = 0; mt < 2; mt++) {
#pragma unroll
                for (int hh = 0; hh < 2; hh++) {
                    int row = wm + mt * 16 + hh * 8 + lrow4;
                    const uint4 v = *(const uint4*)(sA + SWZ(row, ch));
                    aw[mt][hh][0] = v.x;
                    aw[mt][hh][1] = v.y;
                    aw[mt][hh][2] = v.z;
                    aw[mt][hh][3] = v.w;
                }
            }
#pragma unroll
            for (int g = 0; g < 8; g++) {
                int row = wn + g * 8 + lrow4;
                const uint4 bv = *(const uint4*)(sB + SWZ(row, ch));
                mma_tf32(acc[0][g], aw[0][0][0], aw[0][1][0], aw[0][0][1], aw[0][1][1], bv.x, bv.y);
                mma_tf32(acc[0][g], aw[0][0][2], aw[0][1][2], aw[0][0][3], aw[0][1][3], bv.z, bv.w);
                mma_tf32(acc[1][g], aw[1][0][0], aw[1][1][0], aw[1][0][1], aw[1][1][1], bv.x, bv.y);
                mma_tf32(acc[1][g], aw[1][0][2], aw[1][1][2], aw[1][0][3], aw[1][1][3], bv.z, bv.w);
            }
        }
        stage++; if (stage == 3) stage = 0;
    }
    __syncthreads();

    float* sD = (float*)sm_raw;   // 128 x 132
#pragma unroll
    for (int mt = 0; mt < 2; mt++) {
#pragma unroll
        for (int g = 0; g < 8; g++) {
            int ml = wm + mt * 16 + (lane >> 2);
            int nl = wn + g * 8 + (lane & 3) * 2;
            *(float2*)&sD[ml * 132 + nl]       = make_float2(acc[mt][g][0], acc[mt][g][1]);
            *(float2*)&sD[(ml + 8) * 132 + nl] = make_float2(acc[mt][g][2], acc[mt][g][3]);
        }
    }
    __syncthreads();

    for (int i = tid; i < 128 * 128; i += 256) {
        int mm = i >> 7;
        int nn = i & 127;
        int ng = n0 + nn;
        float c = sD[mm * 132 + nn];
        long m = m0 + mm;
        if (ng < 1024) {
            __stcs(&g_a[m * EB + ng], tanh_fast(c + ba[ng]));
        } else if (ng < 2048) {
            __stcs(&g_b[m * EB + (ng - 1024)], c + bb[ng - 1024]);
        } else if (ng < 2112) {
            __stcs(&g_dx[m * DH + (ng - 2048)], c + bd[ng - 2048]);
        }
    }
}

// ---------------- pack Wc^T per head (tf32), launched after gemm ----------------
__global__ void pack_wc_kernel(const float* __restrict__ Wc)
{
    int idx = blockIdx.x * 256 + threadIdx.x;   // < 65536
    int h = idx >> 12;
    int e = (idx >> 6) & 63;
    int d = idx & 63;
    g_wc2[idx] = __uint_as_float(tf32u(Wc[(size_t)h * 4096 + d * 64 + e]));
}

// ---------------- chunked scan: SCH=64, float2 per thread ----------------
__global__ void __launch_bounds__(512)
scanA_kernel()
{
    const int b = blockIdx.x >> 6;
    const int c = blockIdx.x & 63;
    const int e2 = threadIdx.x;
    size_t base = ((size_t)b * LL + (size_t)c * SCL) * EB + 2 * e2;
    float2 P = make_float2(1.f, 1.f), Q = make_float2(0.f, 0.f);
#pragma unroll 8
    for (int l = 0; l < SCL; l++) {
        size_t idx = base + (size_t)l * EB;
        float2 av = __ldcs((const float2*)(g_a + idx));
        float2 bv = __ldcs((const float2*)(g_b + idx));
        Q.x = fmaf(av.x, Q.x, bv.x);
        Q.y = fmaf(av.y, Q.y, bv.y);
        P.x *= av.x;
        P.y *= av.y;
    }
    const int bh = b * 16 + (e2 >> 5);
    const int d  = (2 * e2) & 63;
    *(float2*)(g_cp + ((size_t)(bh * SCH + c) * 64 + d)) = P;
    *(float2*)(g_cq + ((size_t)(bh * SCH + c) * 64 + d)) = Q;
}

// scanC stores hs tf32-rounded (gemm2 A operand; recurrence stays fp32)
__global__ void __launch_bounds__(512)
scanC_kernel()
{
    const int b = blockIdx.x >> 6;
    const int c = blockIdx.x & 63;
    const int e2 = threadIdx.x;
    const int bh = b * 16 + (e2 >> 5);
    const int d  = (2 * e2) & 63;
    float2 hv = make_float2(0.f, 0.f);
    for (int cc = 0; cc < c; cc++) {
        size_t i = (size_t)(bh * SCH + cc) * 64 + d;
        float2 cp = *(const float2*)(g_cp + i);
        float2 cq = *(const float2*)(g_cq + i);
        hv.x = fmaf(cp.x, hv.x, cq.x);
        hv.y = fmaf(cp.y, hv.y, cq.y);
    }
    size_t base = ((size_t)b * LL + (size_t)c * SCL) * EB + 2 * e2;
#pragma unroll 8
    for (int l = 0; l < SCL; l++) {
        size_t idx = base + (size_t)l * EB;
        float2 av = __ldcs((const float2*)(g_a + idx));
        float2 bv = __ldcs((const float2*)(g_b + idx));
        hv.x = fmaf(av.x, hv.x, bv.x);
        hv.y = fmaf(av.y, hv.y, bv.y);
        float2 hw;
        hw.x = __uint_as_float(tf32u(hv.x));
        hw.y = __uint_as_float(tf32u(hv.y));
        __stcs((float2*)(g_hs + idx), hw);
    }
}

// ---------------- gemm2: o[tok][h][:] = hs[tok][h][:] @ WcT[h] + bc[h] + dx[tok] ----------------
// grid (NH, MT/128). CTA: 128 tokens x 64 e, K=64. 8 warps of 16x64.
#define G2ROWB 256
#define G2ATILE (128 * G2ROWB)   // 32768
#define G2BTILE (64 * G2ROWB)    // 16384
#define G2_SMEM (G2ATILE + G2BTILE)  // 49152 (sD 128*68*4=34816 overlays sA)
#define SWZ2(row, chunk) ((uint32_t)((row) * G2ROWB + ((((chunk) ^ (((row) & 1) << 2))) << 4)))

__global__ void __launch_bounds__(256)
gemm2_kernel(const float* __restrict__ bc)
{
    extern __shared__ char sm_raw[];
    const int tid  = threadIdx.x;
    const int wid  = tid >> 5;
    const int lane = tid & 31;
    const uint32_t sbase = smem_u32(sm_raw);

    const int  h  = blockIdx.x;
    const long t0 = (long)blockIdx.y * 128;
    const int  wm = wid * 16;

    // load A: 128 tokens x 64 floats (2048 chunks of 16B)
#pragma unroll
    for (int j = 0; j < 8; j++) {
        int idx = tid + j * 256;
        int row = idx >> 4;
        int ch  = idx & 15;
        cp_async16(sbase + SWZ2(row, ch),
                   g_hs + (t0 + row) * (size_t)EB + h * 64 + ch * 4);
    }
    // load B: 64 e-rows x 64 floats (1024 chunks)
#pragma unroll
    for (int j = 0; j < 4; j++) {
        int idx = tid + j * 256;
        int row = idx >> 4;
        int ch  = idx & 15;
        cp_async16(sbase + G2ATILE + SWZ2(row, ch),
                   g_wc2 + (size_t)h * 4096 + row * 64 + ch * 4);
    }
    cp_commit();
    asm volatile("cp.async.wait_group 0;" ::: "memory");
    __syncthreads();

    const int lrow4 = lane >> 2;
    const int lch   = lane & 3;
    const int par   = (lrow4 & 1) << 2;

    float acc[8][4];
#pragma unroll
    for (int g = 0; g < 8; g++)
#pragma unroll
        for (int q = 0; q < 4; q++) acc[g][q] = 0.f;

#pragma unroll
    for (int k16 = 0; k16 < 4; k16++) {
        const int ch = (k16 * 4 + lch) ^ par;
        uint32_t aw[2][4];
#pragma unroll
        for (int hh = 0; hh < 2; hh++) {
            int row = wm + hh * 8 + lrow4;
            const uint4 v = *(const uint4*)(sm_raw + row * G2ROWB + ch * 16);
            aw[hh][0] = v.x; aw[hh][1] = v.y; aw[hh][2] = v.z; aw[hh][3] = v.w;
        }
#pragma unroll
        for (int g = 0; g < 8; g++) {
            int row = g * 8 + lrow4;
            const uint4 bv = *(const uint4*)(sm_raw + G2ATILE + row * G2ROWB + ch * 16);
            mma_tf32(acc[g], aw[0][0], aw[1][0], aw[0][1], aw[1][1], bv.x, bv.y);
            mma_tf32(acc[g], aw[0][2], aw[1][2], aw[0][3], aw[1][3], bv.z, bv.w);
        }
    }
    __syncthreads();

    // stage into sD (128 x 68), then coalesced write with bias + dx
    float* sD = (float*)sm_raw;
#pragma unroll
    for (int g = 0; g < 8; g++) {
        int ml = wm + (lane >> 2);
        int nl = g * 8 + (lane & 3) * 2;
        *(float2*)&sD[ml * 68 + nl]       = make_float2(acc[g][0], acc[g][1]);
        *(float2*)&sD[(ml + 8) * 68 + nl] = make_float2(acc[g][2], acc[g][3]);
    }
    __syncthreads();

#pragma unroll
    for (int j = 0; j < 8; j++) {
        int idx = tid + j * 256;          // 0..2047 float4 units
        int row = idx >> 4;
        int c4  = (idx & 15) * 4;
        float4 v  = *(const float4*)&sD[row * 68 + c4];
        float4 bcv = *(const float4*)(bc + h * 64 + c4);
        float4 dxv = *(const float4*)(g_dx + (t0 + row) * DH + c4);
        v.x += bcv.x + dxv.x;
        v.y += bcv.y + dxv.y;
        v.z += bcv.z + dxv.z;
        v.w += bcv.w + dxv.w;
        __stcs((float4*)(g_o + (t0 + row) * (size_t)EB + h * 64 + c4), v);
    }
}

// ---------------- fused per-token epilogue (phase A = LN+accumulate only) ----------------
#define TOK 64
#define HS_STRIDE 68
#define POST_FLOATS 21248
#define POST_BYTES  (POST_FLOATS * 4)

__device__ __forceinline__ float grp8_sum(float v) {
    v += __shfl_xor_sync(0xffffffffu, v, 1);
    v += __shfl_xor_sync(0xffffffffu, v, 2);
    v += __shfl_xor_sync(0xffffffffu, v, 4);
    return v;
}

__device__ __forceinline__ void post_prefetch_o(uint32_t shs, int h, long token0, int tid)
{
#pragma unroll
    for (int i = 0; i < 4; i++) {
        int idx = tid + i * 256;
        int t = idx >> 4;
        int c = idx & 15;
        const char* src = (const char*)(g_o + (token0 + t) * (size_t)EB + h * 64);
        cp_async16(shs + (uint32_t)(t * HS_STRIDE * 4 + c * 16), src + c * 16);
    }
}

__global__ void __launch_bounds__(256)
post_kernel(const float* __restrict__ head_w,
            const float* __restrict__ hn_g, const float* __restrict__ hn_b,
            const float* __restrict__ W1,  const float* __restrict__ b1,
            const float* __restrict__ W2,  const float* __restrict__ b2,
            const float* __restrict__ Wp,  const float* __restrict__ bp,
            const float* __restrict__ ng,  const float* __restrict__ nb,
            float* __restrict__ out)
{
    extern __shared__ float sm[];
    const int tid = threadIdx.x;
    const int tt  = tid >> 3;
    const int eg  = tid & 7;
    const int e0  = eg * 8;
    const long token0 = (long)blockIdx.x * TOK;
    const long tok0 = token0 + tt;
    const long tok1 = token0 + tt + 32;

    const uint32_t so_u0 = smem_u32(sm);
    const uint32_t so_u1 = smem_u32(sm + TOK * HS_STRIDE);

    float acc0[8], acc1[8];
#pragma unroll
    for (int k = 0; k < 8; k++) {
        acc0[k] = g_dx[tok0 * DH + e0 + k];
        acc1[k] = g_dx[tok1 * DH + e0 + k];
    }

    post_prefetch_o(so_u0, 0, token0, tid);
    cp_commit();

    for (int h = 0; h < NH; h++) {
        const int cur = h & 1;
        if (h + 1 < NH) {
            post_prefetch_o(cur ? so_u0 : so_u1, h + 1, token0, tid);
            cp_commit();
            asm volatile("cp.async.wait_group 1;" ::: "memory");
        } else {
            asm volatile("cp.async.wait_group 0;" ::: "memory");
        }
        __syncthreads();

        const float* sO = sm + (cur ? TOK * HS_STRIDE : 0);

        float o0[8], o1[8];
#pragma unroll
        for (int k = 0; k < 8; k++) {
            o0[k] = sO[tt * HS_STRIDE + e0 + k];
            o1[k] = sO[(tt + 32) * HS_STRIDE + e0 + k];
        }
        float s10 = 0.f, s20 = 0.f, s11 = 0.f, s21 = 0.f;
#pragma unroll
        for (int k = 0; k < 8; k++) {
            s10 += o0[k]; s20 += o0[k] * o0[k];
            s11 += o1[k]; s21 += o1[k] * o1[k];
        }
        s10 = grp8_sum(s10); s20 = grp8_sum(s20);
        s11 = grp8_sum(s11); s21 = grp8_sum(s21);
        float mean0 = s10 * (1.f / 64.f);
        float var0  = s20 * (1.f / 64.f) - mean0 * mean0;
        float rstd0 = rsqrtf(var0 + 1e-5f);
        float mean1 = s11 * (1.f / 64.f);
        float var1  = s21 * (1.f / 64.f) - mean1 * mean1;
        float rstd1 = rsqrtf(var1 + 1e-5f);
        float hw = head_w[h];
#pragma unroll
        for (int k = 0; k < 8; k++) {
            float gk = hn_g[h * DH + e0 + k];
            float bk = hn_b[h * DH + e0 + k];
            acc0[k] = fmaf(hw, (o0[k] - mean0) * rstd0 * gk + bk, acc0[k]);
            acc1[k] = fmaf(hw, (o1[k] - mean1) * rstd1 * gk + bk, acc1[k]);
        }
        __syncthreads();
    }

    float u0[8], u1[8];
    {
        float s10 = 0.f, s20 = 0.f, s11 = 0.f, s21 = 0.f;
#pragma unroll
        for (int k = 0; k < 8; k++) {
            acc0[k] *= (1.f / (float)NH);
            acc1[k] *= (1.f / (float)NH);
            s10 += acc0[k]; s20 += acc0[k] * acc0[k];
            s11 += acc1[k]; s21 += acc1[k] * acc1[k];
        }
        s10 = grp8_sum(s10); s20 = grp8_sum(s20);
        s11 = grp8_sum(s11); s21 = grp8_sum(s21);
        float mean0 = s10 * (1.f / 64.f);
        float var0  = s20 * (1.f / 64.f) - mean0 * mean0;
        float rstd0 = rsqrtf(var0 + 1e-5f);
        float mean1 = s11 * (1.f / 64.f);
        float var1  = s21 * (1.f / 64.f) - mean1 * mean1;
        float rstd1 = rsqrtf(var1 + 1e-5f);
#pragma unroll
        for (int k = 0; k < 8; k++) {
            float ngk = ng[e0 + k], nbk = nb[e0 + k];
            u0[k] = acc0[k] + (acc0[k] - mean0) * rstd0 * ngk + nbk;
            u1[k] = acc1[k] + (acc1[k] - mean1) * rstd1 * ngk + nbk;
        }
    }

    __syncthreads();

    float* sW1c = sm;
    float* sW2c = sm + 4096;
    float* sU   = sm + 8192;
    float* sGc  = sm + 8192 + TOK * HS_STRIDE;
    float* sHo  = sm + 8192 + 2 * TOK * HS_STRIDE;

#pragma unroll
    for (int k = 0; k < 8; k++) {
        sU[tt * HS_STRIDE + e0 + k]        = u0[k];
        sU[(tt + 32) * HS_STRIDE + e0 + k] = u1[k];
    }

    float o20[8], o21[8];
#pragma unroll
    for (int k = 0; k < 8; k++) { o20[k] = b2[e0 + k]; o21[k] = o20[k]; }

    for (int jc = 0; jc < 4; jc++) {
        __syncthreads();
#pragma unroll
        for (int i = 0; i < 16; i++) {
            int idx = tid + i * 256;
            int d = idx >> 6, jj = idx & 63;
            sW1c[idx] = W1[d * 256 + jc * 64 + jj];
            sW2c[idx] = W2[(jc * 64 + (idx >> 6)) * 64 + (idx & 63)];
        }
        __syncthreads();
#pragma unroll
        for (int kk = 0; kk < 8; kk++) {
            int jl = eg + 8 * kk;
            float m0 = b1[jc * 64 + jl], m1 = m0;
#pragma unroll 8
            for (int d = 0; d < 64; d++) {
                float w = sW1c[d * 64 + jl];
                m0 = fmaf(sU[tt * HS_STRIDE + d], w, m0);
                m1 = fmaf(sU[(tt + 32) * HS_STRIDE + d], w, m1);
            }
            sGc[tt * HS_STRIDE + jl]        = 0.5f * m0 * (1.f + erff(m0 * 0.70710678118654752f));
            sGc[(tt + 32) * HS_STRIDE + jl] = 0.5f * m1 * (1.f + erff(m1 * 0.70710678118654752f));
        }
        __syncthreads();
#pragma unroll 8
        for (int jj = 0; jj < 64; jj++) {
            float gv0 = sGc[tt * HS_STRIDE + jj];
            float gv1 = sGc[(tt + 32) * HS_STRIDE + jj];
            float4 w0 = *(const float4*)&sW2c[jj * 64 + e0];
            float4 w1 = *(const float4*)&sW2c[jj * 64 + e0 + 4];
            o20[0] = fmaf(gv0, w0.x, o20[0]); o20[1] = fmaf(gv0, w0.y, o20[1]);
            o20[2] = fmaf(gv0, w0.z, o20[2]); o20[3] = fmaf(gv0, w0.w, o20[3]);
            o20[4] = fmaf(gv0, w1.x, o20[4]); o20[5] = fmaf(gv0, w1.y, o20[5]);
            o20[6] = fmaf(gv0, w1.z, o20[6]); o20[7] = fmaf(gv0, w1.w, o20[7]);
            o21[0] = fmaf(gv1, w0.x, o21[0]); o21[1] = fmaf(gv1, w0.y, o21[1]);
            o21[2] = fmaf(gv1, w0.z, o21[2]); o21[3] = fmaf(gv1, w0.w, o21[3]);
            o21[4] = fmaf(gv1, w1.x, o21[4]); o21[5] = fmaf(gv1, w1.y, o21[5]);
            o21[6] = fmaf(gv1, w1.z, o21[6]); o21[7] = fmaf(gv1, w1.w, o21[7]);
        }
    }

    __syncthreads();
#pragma unroll
    for (int k = 0; k < 8; k++) {
        sHo[tt * HS_STRIDE + e0 + k]        = u0[k] + o20[k];
        sHo[(tt + 32) * HS_STRIDE + e0 + k] = u1[k] + o21[k];
    }

    float fo0[8], fo1[8];
#pragma unroll
    for (int k = 0; k < 8; k++) { fo0[k] = bp[e0 + k]; fo1[k] = fo0[k]; }
    for (int dc = 0; dc < 2; dc++) {
        __syncthreads();
#pragma unroll
        for (int i = 0; i < 8; i++) {
            int idx = tid + i * 256;
            int d = idx >> 6, e = idx & 63;
            sW1c[idx] = Wp[(dc * 32 + d) * 64 + e];
        }
        __syncthreads();
#pragma unroll 8
        for (int d = 0; d < 32; d++) {
            float hv0 = sHo[tt * HS_STRIDE + dc * 32 + d];
            float hv1 = sHo[(tt + 32) * HS_STRIDE + dc * 32 + d];
            float4 w0 = *(const float4*)&sW1c[d * 64 + e0];
            float4 w1 = *(const float4*)&sW1c[d * 64 + e0 + 4];
            fo0[0] = fmaf(hv0, w0.x, fo0[0]); fo0[1] = fmaf(hv0, w0.y, fo0[1]);
            fo0[2] = fmaf(hv0, w0.z, fo0[2]); fo0[3] = fmaf(hv0, w0.w, fo0[3]);
            fo0[4] = fmaf(hv0, w1.x, fo0[4]); fo0[5] = fmaf(hv0, w1.y, fo0[5]);
            fo0[6] = fmaf(hv0, w1.z, fo0[6]); fo0[7] = fmaf(hv0, w1.w, fo0[7]);
            fo1[0] = fmaf(hv1, w0.x, fo1[0]); fo1[1] = fmaf(hv1, w0.y, fo1[1]);
            fo1[2] = fmaf(hv1, w0.z, fo1[2]); fo1[3] = fmaf(hv1, w0.w, fo1[3]);
            fo1[4] = fmaf(hv1, w1.x, fo1[4]); fo1[5] = fmaf(hv1, w1.y, fo1[5]);
            fo1[6] = fmaf(hv1, w1.z, fo1[6]); fo1[7] = fmaf(hv1, w1.w, fo1[7]);
        }
    }
#pragma unroll
    for (int k = 0; k < 8; k++) {
        out[tok0 * DH + e0 + k] = fo0[k];
        out[tok1 * DH + e0 + k] = fo1[k];
    }
}

// ---------------- launch ----------------
extern "C" void kernel_launch(void* const* d_in, const int* in_sizes, int n_in,
                              void* d_out, int out_size)
{
    const float* emb    = (const float*)d_in[0];
    const float* Wa     = (const float*)d_in[1];
    const float* ba     = (const float*)d_in[2];
    const float* Wb     = (const float*)d_in[3];
    const float* bb     = (const float*)d_in[4];
    const float* Wc     = (const float*)d_in[5];
    const float* bc     = (const float*)d_in[6];
    const float* head_w = (const float*)d_in[7];
    const float* hn_g   = (const float*)d_in[8];
    const float* hn_b   = (const float*)d_in[9];
    const float* Wd     = (const float*)d_in[10];
    const float* bd     = (const float*)d_in[11];
    const float* W1     = (const float*)d_in[12];
    const float* b1     = (const float*)d_in[13];
    const float* W2     = (const float*)d_in[14];
    const float* b2     = (const float*)d_in[15];
    const float* Wp     = (const float*)d_in[16];
    const float* bp     = (const float*)d_in[17];
    const float* ng     = (const float*)d_in[18];
    const float* nb     = (const float*)d_in[19];
    float* out = (float*)d_out;

    cudaFuncSetAttribute(gemm_tf32_kernel, cudaFuncAttributeMaxDynamicSharedMemorySize, GEMM_SMEM);
    cudaFuncSetAttribute(gemm2_kernel, cudaFuncAttributeMaxDynamicSharedMemorySize, G2_SMEM);
    cudaFuncSetAttribute(post_kernel, cudaFuncAttributeMaxDynamicSharedMemorySize, POST_BYTES);

    preround_kernel<<<(int)((size_t)MT * GK / 4 / 256), 256>>>(emb);
    pack_a_kernel<<<4096, 256>>>(Wa);
    pack_bd_kernel<<<4608, 256>>>(Wb, Wd);

    dim3 ggrid(GNP / 128, MT / 128);
    gemm_tf32_kernel<<<ggrid, 256, GEMM_SMEM>>>(ba, bb, bd);

    pack_wc_kernel<<<256, 256>>>(Wc);
    scanA_kernel<<<BB * SCH, 512>>>();
    scanC_kernel<<<BB * SCH, 512>>>();

    dim3 g2grid(NH, MT / 128);
    gemm2_kernel<<<g2grid, 256, G2_SMEM>>>(bc);

    post_kernel<<<MT / TOK, 256, POST_BYTES>>>(head_w, hn_g, hn_b,
                                               W1, b1, W2, b2, Wp, bp, ng, nb, out);
}

// round 16
// speedup vs baseline: 1.2893x; 1.0098x over previous
#include <cuda_runtime.h>
#include <cuda_bf16.h>
#include <math.h>
#include <stdint.h>

// Problem constants
#define EB 1024     // embed dim
#define DH 64       // head dim
#define NH 16       // heads
#define BB 8
#define LL 4096
#define MT (BB*LL)          // 32768 tokens
#define GNP 2176            // padded N (17 tiles of 128)
#define GK EB

// ---------------- scratch ----------------
__device__ float g_a [ (size_t)MT * EB ];
__device__ float g_b [ (size_t)MT * EB ];
__device__ float g_hs[ (size_t)MT * EB ];   // scan out, tf32-rounded at store
__device__ float g_u [ (size_t)MT * DH ];   // fused u output (replaces g_o)
__device__ float g_dx[ (size_t)MT * DH ];
__device__ float g_wt[ (size_t)GNP * GK ];  // gates weights [n][k], tf32
__device__ float g_et[ (size_t)MT * GK ];   // emb, tf32
__device__ float g_wc2[ NH * DH * DH ];     // Wc^T per head [h][e][d], tf32

#define SCH 64
#define SCL (LL / SCH)      // 64
__device__ float g_cp[128 * SCH * 64];
__device__ float g_cq[128 * SCH * 64];

// ---------------- helpers ----------------
__device__ __forceinline__ uint32_t smem_u32(const void* p) {
    uint32_t r;
    asm("{ .reg .u64 t; cvta.to.shared.u64 t, %1; cvt.u32.u64 %0, t; }" : "=r"(r) : "l"(p));
    return r;
}
__device__ __forceinline__ void cp_async16(uint32_t dst, const void* src) {
    asm volatile("cp.async.cg.shared.global [%0], [%1], 16;" :: "r"(dst), "l"(src) : "memory");
}
__device__ __forceinline__ void cp_commit() {
    asm volatile("cp.async.commit_group;" ::: "memory");
}
__device__ __forceinline__ uint32_t tf32u(float x) {
    uint32_t u;
    asm("cvt.rna.tf32.f32 %0, %1;" : "=r"(u) : "f"(x));
    return u;
}
__device__ __forceinline__ void mma_tf32(float* c,
                                         uint32_t a0, uint32_t a1, uint32_t a2, uint32_t a3,
                                         uint32_t b0, uint32_t b1) {
    asm volatile(
        "mma.sync.aligned.m16n8k8.row.col.f32.tf32.tf32.f32 "
        "{%0,%1,%2,%3}, {%4,%5,%6,%7}, {%8,%9}, {%0,%1,%2,%3};"
        : "+f"(c[0]), "+f"(c[1]), "+f"(c[2]), "+f"(c[3])
        : "r"(a0), "r"(a1), "r"(a2), "r"(a3), "r"(b0), "r"(b1));
}
__device__ __forceinline__ float tanh_fast(float x) {
    float xc = fminf(fmaxf(x, -10.f), 10.f);
    float t  = __expf(2.f * xc);
    return __fdividef(t - 1.f, t + 1.f);
}
__device__ __forceinline__ float quad_sum(float v) {
    v += __shfl_xor_sync(0xffffffffu, v, 1);
    v += __shfl_xor_sync(0xffffffffu, v, 2);
    return v;
}

// ---------------- launch 0: pre-round emb to tf32 ----------------
__global__ void preround_kernel(const float* __restrict__ emb)
{
    size_t i = ((size_t)blockIdx.x * 256 + threadIdx.x) * 4;
    float4 x = *(const float4*)(emb + i);
    float4 y;
    y.x = __uint_as_float(tf32u(x.x));
    y.y = __uint_as_float(tf32u(x.y));
    y.z = __uint_as_float(tf32u(x.z));
    y.w = __uint_as_float(tf32u(x.w));
    *(float4*)(g_et + i) = y;
}

// ---------------- launches 1,2: pack gates weights [n][k] ----------------
__global__ void pack_a_kernel(const float* __restrict__ Wa)
{
    size_t idx = (size_t)blockIdx.x * 256 + threadIdx.x;
    int n = (int)(idx >> 10);
    int k = (int)(idx & 1023);
    float v = Wa[(size_t)(n >> 6) * (EB * DH) + (size_t)k * DH + (n & 63)];
    g_wt[idx] = __uint_as_float(tf32u(v));
}
__global__ void pack_bd_kernel(const float* __restrict__ Wb, const float* __restrict__ Wd)
{
    size_t idx = (size_t)blockIdx.x * 256 + threadIdx.x;
    int n = (int)(idx >> 10);
    int k = (int)(idx & 1023);
    float v;
    if (n < 1024) {
        v = Wb[(size_t)(n >> 6) * (EB * DH) + (size_t)k * DH + (n & 63)];
    } else {
        int n2 = n - 1024;
        v = (n2 < 64) ? Wd[(size_t)k * DH + n2] : 0.f;
    }
    g_wt[(size_t)(1024 + n) * 1024 + k] = __uint_as_float(tf32u(v));
}

// ---------------- launch 3: TF32 gates GEMM (unchanged from R13) ----------------
#define KC 32
#define NKC (GK / KC)          // 32
#define ROWB 128
#define TILEB (128 * ROWB)     // 16384
#define STAGEB (2 * TILEB)     // 32768
#define GEMM_SMEM (3 * STAGEB) // 98304

#define SWZ(row, chunk) ((uint32_t)((row) * ROWB + ((((chunk) ^ (((row) & 1) << 2))) << 4)))

__device__ __forceinline__ void gemm_load_stage(uint32_t sst, int kc, int tid,
                                                const char* Ag, const char* Bg)
{
    const size_t kb = (size_t)kc * 128;
#pragma unroll
    for (int j = 0; j < 4; j++) {
        int id  = tid + j * 256;
        int row = id >> 3;
        int c   = id & 7;
        cp_async16(sst + SWZ(row, c),         Ag + (size_t)row * 4096 + kb + c * 16);
        cp_async16(sst + TILEB + SWZ(row, c), Bg + (size_t)row * 4096 + kb + c * 16);
    }
}

__global__ void __launch_bounds__(256, 2)
gemm_tf32_kernel(const float* __restrict__ ba,
                 const float* __restrict__ bb,
                 const float* __restrict__ bd)
{
    extern __shared__ char sm_raw[];
    const int tid  = threadIdx.x;
    const int wid  = tid >> 5;
    const int lane = tid & 31;
    const uint32_t sbase = smem_u32(sm_raw);

    const long m0 = (long)blockIdx.y * 128;
    const int  n0 = blockIdx.x * 128;
    const int  wm = (wid & 3) * 32;
    const int  wn = (wid >> 2) * 64;

    const char* Ag = (const char*)(g_et + (size_t)m0 * GK);
    const char* Bg = (const char*)(g_wt + (size_t)n0 * GK);

    float acc[2][8][4];
#pragma unroll
    for (int i = 0; i < 2; i++)
#pragma unroll
        for (int j = 0; j < 8; j++)
#pragma unroll
            for (int q = 0; q < 4; q++) acc[i][j][q] = 0.f;

    gemm_load_stage(sbase, 0, tid, Ag, Bg);
    cp_commit();
    gemm_load_stage(sbase + STAGEB, 1, tid, Ag, Bg);
    cp_commit();

    const int lrow4 = lane >> 2;
    const int lch   = lane & 3;

    int stage = 0;
#pragma unroll 3
    for (int kc = 0; kc < NKC; kc++) {
        if (kc + 1 < NKC) {
            asm volatile("cp.async.wait_group 1;" ::: "memory");
        } else {
            asm volatile("cp.async.wait_group 0;" ::: "memory");
        }
        __syncthreads();
        if (kc + 2 < NKC) {
            int nstage = stage + 2; if (nstage >= 3) nstage -= 3;
            gemm_load_stage(sbase + nstage * STAGEB, kc + 2, tid, Ag, Bg);
            cp_commit();
        }

        const char* sA = sm_raw + stage * STAGEB;
        const char* sB = sA + TILEB;

#pragma unroll
        for (int k16 = 0; k16 < 2; k16++) {
            const int ch = k16 * 4 + lch;
            uint32_t aw[2][2][4];
#pragma unroll
            for (int mt = 0; mt < 2; mt++) {
#pragma unroll
                for (int hh = 0; hh < 2; hh++) {
                    int row = wm + mt * 16 + hh * 8 + lrow4;
                    const uint4 v = *(const uint4*)(sA + SWZ(row, ch));
                    aw[mt][hh][0] = v.x;
                    aw[mt][hh][1] = v.y;
                    aw[mt][hh][2] = v.z;
                    aw[mt][hh][3] = v.w;
                }
            }
#pragma unroll
            for (int g = 0; g < 8; g++) {
                int row = wn + g * 8 + lrow4;
                const uint4 bv = *(const uint4*)(sB + SWZ(row, ch));
                mma_tf32(acc[0][g], aw[0][0][0], aw[0][1][0], aw[0][0][1], aw[0][1][1], bv.x, bv.y);
                mma_tf32(acc[0][g], aw[0][0][2], aw[0][1][2], aw[0][0][3], aw[0][1][3], bv.z, bv.w);
                mma_tf32(acc[1][g], aw[1][0][0], aw[1][1][0], aw[1][0][1], aw[1][1][1], bv.x, bv.y);
                mma_tf32(acc[1][g], aw[1][0][2], aw[1][1][2], aw[1][0][3], aw[1][1][3], bv.z, bv.w);
            }
        }
        stage++; if (stage == 3) stage = 0;
    }
    __syncthreads();

    float* sD = (float*)sm_raw;   // 128 x 132
#pragma unroll
    for (int mt = 0; mt < 2; mt++) {
#pragma unroll
        for (int g = 0; g < 8; g++) {
            int ml = wm + mt * 16 + (lane >> 2);
            int nl = wn + g * 8 + (lane & 3) * 2;
            *(float2*)&sD[ml * 132 + nl]       = make_float2(acc[mt][g][0], acc[mt][g][1]);
            *(float2*)&sD[(ml + 8) * 132 + nl] = make_float2(acc[mt][g][2], acc[mt][g][3]);
        }
    }
    __syncthreads();

    for (int i = tid; i < 128 * 128; i += 256) {
        int mm = i >> 7;
        int nn = i & 127;
        int ng = n0 + nn;
        float c = sD[mm * 132 + nn];
        long m = m0 + mm;
        if (ng < 1024) {
            __stcs(&g_a[m * EB + ng], tanh_fast(c + ba[ng]));
        } else if (ng < 2048) {
            __stcs(&g_b[m * EB + (ng - 1024)], c + bb[ng - 1024]);
        } else if (ng < 2112) {
            __stcs(&g_dx[m * DH + (ng - 2048)], c + bd[ng - 2048]);
        }
    }
}

// ---------------- pack Wc^T per head (tf32) ----------------
__global__ void pack_wc_kernel(const float* __restrict__ Wc)
{
    int idx = blockIdx.x * 256 + threadIdx.x;   // < 65536
    int h = idx >> 12;
    int e = (idx >> 6) & 63;
    int d = idx & 63;
    g_wc2[idx] = __uint_as_float(tf32u(Wc[(size_t)h * 4096 + d * 64 + e]));
}

// ---------------- chunked scan: SCH=64, float2 per thread ----------------
__global__ void __launch_bounds__(512)
scanA_kernel()
{
    const int b = blockIdx.x >> 6;
    const int c = blockIdx.x & 63;
    const int e2 = threadIdx.x;
    size_t base = ((size_t)b * LL + (size_t)c * SCL) * EB + 2 * e2;
    float2 P = make_float2(1.f, 1.f), Q = make_float2(0.f, 0.f);
#pragma unroll 8
    for (int l = 0; l < SCL; l++) {
        size_t idx = base + (size_t)l * EB;
        float2 av = __ldcs((const float2*)(g_a + idx));
        float2 bv = __ldcs((const float2*)(g_b + idx));
        Q.x = fmaf(av.x, Q.x, bv.x);
        Q.y = fmaf(av.y, Q.y, bv.y);
        P.x *= av.x;
        P.y *= av.y;
    }
    const int bh = b * 16 + (e2 >> 5);
    const int d  = (2 * e2) & 63;
    *(float2*)(g_cp + ((size_t)(bh * SCH + c) * 64 + d)) = P;
    *(float2*)(g_cq + ((size_t)(bh * SCH + c) * 64 + d)) = Q;
}

__global__ void __launch_bounds__(512)
scanC_kernel()
{
    const int b = blockIdx.x >> 6;
    const int c = blockIdx.x & 63;
    const int e2 = threadIdx.x;
    const int bh = b * 16 + (e2 >> 5);
    const int d  = (2 * e2) & 63;
    float2 hv = make_float2(0.f, 0.f);
    for (int cc = 0; cc < c; cc++) {
        size_t i = (size_t)(bh * SCH + cc) * 64 + d;
        float2 cp = *(const float2*)(g_cp + i);
        float2 cq = *(const float2*)(g_cq + i);
        hv.x = fmaf(cp.x, hv.x, cq.x);
        hv.y = fmaf(cp.y, hv.y, cq.y);
    }
    size_t base = ((size_t)b * LL + (size_t)c * SCL) * EB + 2 * e2;
#pragma unroll 8
    for (int l = 0; l < SCL; l++) {
        size_t idx = base + (size_t)l * EB;
        float2 av = __ldcs((const float2*)(g_a + idx));
        float2 bv = __ldcs((const float2*)(g_b + idx));
        hv.x = fmaf(av.x, hv.x, bv.x);
        hv.y = fmaf(av.y, hv.y, bv.y);
        float2 hw;
        hw.x = __uint_as_float(tf32u(hv.x));
        hw.y = __uint_as_float(tf32u(hv.y));
        __stcs((float2*)(g_hs + idx), hw);
    }
}

// ---------------- gemm2u: per 128-token tile, all 16 heads fused ----------------
// For each head: o = hs@WcT + bc + dx; LN(o); sum += head_w*LN.
// Then z = sum/16, u = z + LN(z). Writes g_u [MT x 64].
// Smem: sHs 0..32767 | sWc 32768..49151 | sDx 49152..83967 (128x68 f32) | params 83968..96255
#define G2ROWB 256
#define G2_HS   0
#define G2_WC   32768
#define G2_DX   49152
#define G2_PAR  83968
#define G2U_SMEM 96256
#define SWZ2(row, chunk) ((uint32_t)((row) * G2ROWB + ((((chunk) ^ (((row) & 1) << 2))) << 4)))

__global__ void __launch_bounds__(256, 2)
gemm2u_kernel(const float* __restrict__ bc,  const float* __restrict__ head_w,
              const float* __restrict__ hn_g, const float* __restrict__ hn_b,
              const float* __restrict__ ng,  const float* __restrict__ nb)
{
    extern __shared__ char sm_raw[];
    const int tid  = threadIdx.x;
    const int wid  = tid >> 5;
    const int lane = tid & 31;
    const uint32_t sbase = smem_u32(sm_raw);

    const long t0 = (long)blockIdx.x * 128;
    const int  wm = wid * 16;
    const int  lrow4 = lane >> 2;
    const int  lch   = lane & 3;
    const int  par   = (lrow4 & 1) << 2;

    float* sDx = (float*)(sm_raw + G2_DX);
    float* sBc = (float*)(sm_raw + G2_PAR);
    float* sHg = sBc + 1024;
    float* sHb = sHg + 1024;

    // params + dx tile
    for (int i = tid; i < 1024; i += 256) {
        sBc[i] = bc[i];
        sHg[i] = hn_g[i];
        sHb[i] = hn_b[i];
    }
#pragma unroll
    for (int j = 0; j < 8; j++) {
        int idx = tid + j * 256;
        int row = idx >> 4;
        int c4  = (idx & 15) * 4;
        *(float4*)&sDx[row * 68 + c4] = *(const float4*)(g_dx + (t0 + row) * DH + c4);
    }
    __syncthreads();

    const int rowA = wm + lrow4;     // fragment rows: rowA (q0,q1), rowA+8 (q2,q3)

    // running head-sum seeded with dx (fragment layout)
    float sum[8][4];
#pragma unroll
    for (int g = 0; g < 8; g++) {
        int col = g * 8 + lch * 2;
        sum[g][0] = sDx[rowA * 68 + col];
        sum[g][1] = sDx[rowA * 68 + col + 1];
        sum[g][2] = sDx[(rowA + 8) * 68 + col];
        sum[g][3] = sDx[(rowA + 8) * 68 + col + 1];
    }

    for (int h = 0; h < NH; h++) {
        // load hs slice + WcT_h
#pragma unroll
        for (int j = 0; j < 8; j++) {
            int idx = tid + j * 256;
            int row = idx >> 4;
            int ch  = idx & 15;
            cp_async16(sbase + G2_HS + SWZ2(row, ch),
                       g_hs + (t0 + row) * (size_t)EB + h * 64 + ch * 4);
        }
#pragma unroll
        for (int j = 0; j < 4; j++) {
            int idx = tid + j * 256;
            int row = idx >> 4;
            int ch  = idx & 15;
            cp_async16(sbase + G2_WC + SWZ2(row, ch),
                       g_wc2 + (size_t)h * 4096 + row * 64 + ch * 4);
        }
        cp_commit();
        asm volatile("cp.async.wait_group 0;" ::: "memory");
        __syncthreads();

        float acc[8][4];
#pragma unroll
        for (int g = 0; g < 8; g++)
#pragma unroll
            for (int q = 0; q < 4; q++) acc[g][q] = 0.f;

#pragma unroll
        for (int k16 = 0; k16 < 4; k16++) {
            const int ch = (k16 * 4 + lch) ^ par;
            uint32_t aw[2][4];
#pragma unroll
            for (int hh = 0; hh < 2; hh++) {
                int row = wm + hh * 8 + lrow4;
                const uint4 v = *(const uint4*)(sm_raw + G2_HS + row * G2ROWB + ch * 16);
                aw[hh][0] = v.x; aw[hh][1] = v.y; aw[hh][2] = v.z; aw[hh][3] = v.w;
            }
#pragma unroll
            for (int g = 0; g < 8; g++) {
                int row = g * 8 + lrow4;
                const uint4 bv = *(const uint4*)(sm_raw + G2_WC + row * G2ROWB + ch * 16);
                mma_tf32(acc[g], aw[0][0], aw[1][0], aw[0][1], aw[1][1], bv.x, bv.y);
                mma_tf32(acc[g], aw[0][2], aw[1][2], aw[0][3], aw[1][3], bv.z, bv.w);
            }
        }
        __syncthreads();   // all mma smem reads done before next head's loads

        // per-head epilogue in fragment regs: o = acc + bc + dx ; LN over 64 cols
        float o[8][4];
        float s1a = 0.f, s2a = 0.f, s1b = 0.f, s2b = 0.f;
#pragma unroll
        for (int g = 0; g < 8; g++) {
            int col = g * 8 + lch * 2;
#pragma unroll
            for (int q = 0; q < 4; q++) {
                int cc = col + (q & 1);
                int rr = (q < 2) ? rowA : (rowA + 8);
                float v = acc[g][q] + sBc[h * 64 + cc] + sDx[rr * 68 + cc];
                o[g][q] = v;
                if (q < 2) { s1a += v; s2a += v * v; }
                else       { s1b += v; s2b += v * v; }
            }
        }
        s1a = quad_sum(s1a); s2a = quad_sum(s2a);
        s1b = quad_sum(s1b); s2b = quad_sum(s2b);
        float meanA = s1a * (1.f / 64.f);
        float rstdA = rsqrtf(s2a * (1.f / 64.f) - meanA * meanA + 1e-5f);
        float meanB = s1b * (1.f / 64.f);
        float rstdB = rsqrtf(s2b * (1.f / 64.f) - meanB * meanB + 1e-5f);
        float hw = head_w[h];
#pragma unroll
        for (int g = 0; g < 8; g++) {
            int col = g * 8 + lch * 2;
#pragma unroll
            for (int q = 0; q < 4; q++) {
                int cc = col + (q & 1);
                float mean = (q < 2) ? meanA : meanB;
                float rstd = (q < 2) ? rstdA : rstdB;
                float lnv = (o[g][q] - mean) * rstd * sHg[h * 64 + cc] + sHb[h * 64 + cc];
                sum[g][q] = fmaf(hw, lnv, sum[g][q]);
            }
        }
    }

    // z = sum/16 ; u = z + LN(z)*ng + nb
    {
        float s1a = 0.f, s2a = 0.f, s1b = 0.f, s2b = 0.f;
#pragma unroll
        for (int g = 0; g < 8; g++)
#pragma unroll
            for (int q = 0; q < 4; q++) {
                sum[g][q] *= (1.f / (float)NH);
                float v = sum[g][q];
                if (q < 2) { s1a += v; s2a += v * v; }
                else       { s1b += v; s2b += v * v; }
            }
        s1a = quad_sum(s1a); s2a = quad_sum(s2a);
        s1b = quad_sum(s1b); s2b = quad_sum(s2b);
        float meanA = s1a * (1.f / 64.f);
        float rstdA = rsqrtf(s2a * (1.f / 64.f) - meanA * meanA + 1e-5f);
        float meanB = s1b * (1.f / 64.f);
        float rstdB = rsqrtf(s2b * (1.f / 64.f) - meanB * meanB + 1e-5f);
        __syncthreads();   // done with sDx as dx source; reuse for staging u
#pragma unroll
        for (int g = 0; g < 8; g++) {
            int col = g * 8 + lch * 2;
#pragma unroll
            for (int q = 0; q < 4; q++) {
                int cc = col + (q & 1);
                float mean = (q < 2) ? meanA : meanB;
                float rstd = (q < 2) ? rstdA : rstdB;
                int rr = (q < 2) ? rowA : (rowA + 8);
                float z = sum[g][q];
                sDx[rr * 68 + cc] = z + (z - mean) * rstd * ng[cc] + nb[cc];
            }
        }
    }
    __syncthreads();

#pragma unroll
    for (int j = 0; j < 8; j++) {
        int idx = tid + j * 256;
        int row = idx >> 4;
        int c4  = (idx & 15) * 4;
        __stcs((float4*)(g_u + (t0 + row) * DH + c4), *(const float4*)&sDx[row * 68 + c4]);
    }
}

// ---------------- post: FFN only (reads g_u) ----------------
#define TOK 64
#define HS_STRIDE 68
#define POST_FLOATS (8192 + 3 * TOK * HS_STRIDE)   // 21248
#define POST_BYTES  (POST_FLOATS * 4)

__global__ void __launch_bounds__(256)
post_kernel(const float* __restrict__ W1,  const float* __restrict__ b1,
            const float* __restrict__ W2,  const float* __restrict__ b2,
            const float* __restrict__ Wp,  const float* __restrict__ bp,
            float* __restrict__ out)
{
    extern __shared__ float sm[];
    const int tid = threadIdx.x;
    const int tt  = tid >> 3;
    const int eg  = tid & 7;
    const int e0  = eg * 8;
    const long token0 = (long)blockIdx.x * TOK;
    const long tok0 = token0 + tt;
    const long tok1 = token0 + tt + 32;

    float* sW1c = sm;
    float* sW2c = sm + 4096;
    float* sU   = sm + 8192;
    float* sGc  = sm + 8192 + TOK * HS_STRIDE;
    float* sHo  = sm + 8192 + 2 * TOK * HS_STRIDE;

    float u0[8], u1[8];
    {
        float4 a0 = *(const float4*)(g_u + tok0 * DH + e0);
        float4 a1 = *(const float4*)(g_u + tok0 * DH + e0 + 4);
        float4 b0 = *(const float4*)(g_u + tok1 * DH + e0);
        float4 b1v = *(const float4*)(g_u + tok1 * DH + e0 + 4);
        u0[0]=a0.x; u0[1]=a0.y; u0[2]=a0.z; u0[3]=a0.w;
        u0[4]=a1.x; u0[5]=a1.y; u0[6]=a1.z; u0[7]=a1.w;
        u1[0]=b0.x; u1[1]=b0.y; u1[2]=b0.z; u1[3]=b0.w;
        u1[4]=b1v.x; u1[5]=b1v.y; u1[6]=b1v.z; u1[7]=b1v.w;
    }

#pragma unroll
    for (int k = 0; k < 8; k++) {
        sU[tt * HS_STRIDE + e0 + k]        = u0[k];
        sU[(tt + 32) * HS_STRIDE + e0 + k] = u1[k];
    }

    float o20[8], o21[8];
#pragma unroll
    for (int k = 0; k < 8; k++) { o20[k] = b2[e0 + k]; o21[k] = o20[k]; }

    for (int jc = 0; jc < 4; jc++) {
        __syncthreads();
#pragma unroll
        for (int i = 0; i < 16; i++) {
            int idx = tid + i * 256;
            int d = idx >> 6, jj = idx & 63;
            sW1c[idx] = W1[d * 256 + jc * 64 + jj];
            sW2c[idx] = W2[(jc * 64 + (idx >> 6)) * 64 + (idx & 63)];
        }
        __syncthreads();
#pragma unroll
        for (int kk = 0; kk < 8; kk++) {
            int jl = eg + 8 * kk;
            float m0 = b1[jc * 64 + jl], m1 = m0;
#pragma unroll 8
            for (int d = 0; d < 64; d++) {
                float w = sW1c[d * 64 + jl];
                m0 = fmaf(sU[tt * HS_STRIDE + d], w, m0);
                m1 = fmaf(sU[(tt + 32) * HS_STRIDE + d], w, m1);
            }
            sGc[tt * HS_STRIDE + jl]        = 0.5f * m0 * (1.f + erff(m0 * 0.70710678118654752f));
            sGc[(tt + 32) * HS_STRIDE + jl] = 0.5f * m1 * (1.f + erff(m1 * 0.70710678118654752f));
        }
        __syncthreads();
#pragma unroll 8
        for (int jj = 0; jj < 64; jj++) {
            float gv0 = sGc[tt * HS_STRIDE + jj];
            float gv1 = sGc[(tt + 32) * HS_STRIDE + jj];
            float4 w0 = *(const float4*)&sW2c[jj * 64 + e0];
            float4 w1 = *(const float4*)&sW2c[jj * 64 + e0 + 4];
            o20[0] = fmaf(gv0, w0.x, o20[0]); o20[1] = fmaf(gv0, w0.y, o20[1]);
            o20[2] = fmaf(gv0, w0.z, o20[2]); o20[3] = fmaf(gv0, w0.w, o20[3]);
            o20[4] = fmaf(gv0, w1.x, o20[4]); o20[5] = fmaf(gv0, w1.y, o20[5]);
            o20[6] = fmaf(gv0, w1.z, o20[6]); o20[7] = fmaf(gv0, w1.w, o20[7]);
            o21[0] = fmaf(gv1, w0.x, o21[0]); o21[1] = fmaf(gv1, w0.y, o21[1]);
            o21[2] = fmaf(gv1, w0.z, o21[2]); o21[3] = fmaf(gv1, w0.w, o21[3]);
            o21[4] = fmaf(gv1, w1.x, o21[4]); o21[5] = fmaf(gv1, w1.y, o21[5]);
            o21[6] = fmaf(gv1, w1.z, o21[6]); o21[7] = fmaf(gv1, w1.w, o21[7]);
        }
    }

    __syncthreads();
#pragma unroll
    for (int k = 0; k < 8; k++) {
        sHo[tt * HS_STRIDE + e0 + k]        = u0[k] + o20[k];
        sHo[(tt + 32) * HS_STRIDE + e0 + k] = u1[k] + o21[k];
    }

    float fo0[8], fo1[8];
#pragma unroll
    for (int k = 0; k < 8; k++) { fo0[k] = bp[e0 + k]; fo1[k] = fo0[k]; }
    for (int dc = 0; dc < 2; dc++) {
        __syncthreads();
#pragma unroll
        for (int i = 0; i < 8; i++) {
            int idx = tid + i * 256;
            int d = idx >> 6, e = idx & 63;
            sW1c[idx] = Wp[(dc * 32 + d) * 64 + e];
        }
        __syncthreads();
#pragma unroll 8
        for (int d = 0; d < 32; d++) {
            float hv0 = sHo[tt * HS_STRIDE + dc * 32 + d];
            float hv1 = sHo[(tt + 32) * HS_STRIDE + dc * 32 + d];
            float4 w0 = *(const float4*)&sW1c[d * 64 + e0];
            float4 w1 = *(const float4*)&sW1c[d * 64 + e0 + 4];
            fo0[0] = fmaf(hv0, w0.x, fo0[0]); fo0[1] = fmaf(hv0, w0.y, fo0[1]);
            fo0[2] = fmaf(hv0, w0.z, fo0[2]); fo0[3] = fmaf(hv0, w0.w, fo0[3]);
            fo0[4] = fmaf(hv0, w1.x, fo0[4]); fo0[5] = fmaf(hv0, w1.y, fo0[5]);
            fo0[6] = fmaf(hv0, w1.z, fo0[6]); fo0[7] = fmaf(hv0, w1.w, fo0[7]);
            fo1[0] = fmaf(hv1, w0.x, fo1[0]); fo1[1] = fmaf(hv1, w0.y, fo1[1]);
            fo1[2] = fmaf(hv1, w0.z, fo1[2]); fo1[3] = fmaf(hv1, w0.w, fo1[3]);
            fo1[4] = fmaf(hv1, w1.x, fo1[4]); fo1[5] = fmaf(hv1, w1.y, fo1[5]);
            fo1[6] = fmaf(hv1, w1.z, fo1[6]); fo1[7] = fmaf(hv1, w1.w, fo1[7]);
        }
    }
#pragma unroll
    for (int k = 0; k < 8; k++) {
        out[tok0 * DH + e0 + k] = fo0[k];
        out[tok1 * DH + e0 + k] = fo1[k];
    }
}

// ---------------- launch ----------------
extern "C" void kernel_launch(void* const* d_in, const int* in_sizes, int n_in,
                              void* d_out, int out_size)
{
    const float* emb    = (const float*)d_in[0];
    const float* Wa     = (const float*)d_in[1];
    const float* ba     = (const float*)d_in[2];
    const float* Wb     = (const float*)d_in[3];
    const float* bb     = (const float*)d_in[4];
    const float* Wc     = (const float*)d_in[5];
    const float* bc     = (const float*)d_in[6];
    const float* head_w = (const float*)d_in[7];
    const float* hn_g   = (const float*)d_in[8];
    const float* hn_b   = (const float*)d_in[9];
    const float* Wd     = (const float*)d_in[10];
    const float* bd     = (const float*)d_in[11];
    const float* W1     = (const float*)d_in[12];
    const float* b1     = (const float*)d_in[13];
    const float* W2     = (const float*)d_in[14];
    const float* b2     = (const float*)d_in[15];
    const float* Wp     = (const float*)d_in[16];
    const float* bp     = (const float*)d_in[17];
    const float* ng     = (const float*)d_in[18];
    const float* nb     = (const float*)d_in[19];
    float* out = (float*)d_out;

    cudaFuncSetAttribute(gemm_tf32_kernel, cudaFuncAttributeMaxDynamicSharedMemorySize, GEMM_SMEM);
    cudaFuncSetAttribute(gemm2u_kernel, cudaFuncAttributeMaxDynamicSharedMemorySize, G2U_SMEM);
    cudaFuncSetAttribute(post_kernel, cudaFuncAttributeMaxDynamicSharedMemorySize, POST_BYTES);

    preround_kernel<<<(int)((size_t)MT * GK / 4 / 256), 256>>>(emb);
    pack_a_kernel<<<4096, 256>>>(Wa);
    pack_bd_kernel<<<4608, 256>>>(Wb, Wd);

    dim3 ggrid(GNP / 128, MT / 128);
    gemm_tf32_kernel<<<ggrid, 256, GEMM_SMEM>>>(ba, bb, bd);

    pack_wc_kernel<<<256, 256>>>(Wc);
    scanA_kernel<<<BB * SCH, 512>>>();
    scanC_kernel<<<BB * SCH, 512>>>();

    gemm2u_kernel<<<MT / 128, 256, G2U_SMEM>>>(bc, head_w, hn_g, hn_b, ng, nb);

    post_kernel<<<MT / TOK, 256, POST_BYTES>>>(W1, b1, W2, b2, Wp, bp, out);
}

// round 17
// speedup vs baseline: 1.4991x; 1.1627x over previous
#include <cuda_runtime.h>
#include <cuda_bf16.h>
#include <math.h>
#include <stdint.h>

// Problem constants
#define EB 1024
#define DH 64
#define NH 16
#define BB 8
#define LL 4096
#define MT (BB*LL)          // 32768 tokens
#define GNP 2176
#define GK EB

// ---------------- scratch ----------------
__device__ float g_a [ (size_t)MT * EB ];
__device__ float g_b [ (size_t)MT * EB ];
__device__ float g_hs[ (size_t)MT * EB ];   // scan out, tf32-rounded
__device__ float g_u [ (size_t)MT * DH ];   // fused u
__device__ float g_dx[ (size_t)MT * DH ];
__device__ float g_wt[ (size_t)GNP * GK ];  // gates weights [n][k], tf32
__device__ float g_et[ (size_t)MT * GK ];   // emb, tf32
__device__ float g_wc2[ NH * DH * DH ];     // Wc^T per head, tf32
__device__ float g_w1t[ 256 * 64 ];         // W1^T [j][d], tf32
__device__ float g_w2t[ 64 * 256 ];         // W2^T [e][j], tf32
__device__ float g_wpt[ 64 * 64 ];          // Wp^T [e][d], tf32

#define SCH 64
#define SCL (LL / SCH)      // 64
__device__ float g_cp[128 * SCH * 64];
__device__ float g_cq[128 * SCH * 64];

// ---------------- helpers ----------------
__device__ __forceinline__ uint32_t smem_u32(const void* p) {
    uint32_t r;
    asm("{ .reg .u64 t; cvta.to.shared.u64 t, %1; cvt.u32.u64 %0, t; }" : "=r"(r) : "l"(p));
    return r;
}
__device__ __forceinline__ void cp_async16(uint32_t dst, const void* src) {
    asm volatile("cp.async.cg.shared.global [%0], [%1], 16;" :: "r"(dst), "l"(src) : "memory");
}
__device__ __forceinline__ void cp_commit() {
    asm volatile("cp.async.commit_group;" ::: "memory");
}
__device__ __forceinline__ uint32_t tf32u(float x) {
    uint32_t u;
    asm("cvt.rna.tf32.f32 %0, %1;" : "=r"(u) : "f"(x));
    return u;
}
__device__ __forceinline__ float tf32f(float x) { return __uint_as_float(tf32u(x)); }
__device__ __forceinline__ void mma_tf32(float* c,
                                         uint32_t a0, uint32_t a1, uint32_t a2, uint32_t a3,
                                         uint32_t b0, uint32_t b1) {
    asm volatile(
        "mma.sync.aligned.m16n8k8.row.col.f32.tf32.tf32.f32 "
        "{%0,%1,%2,%3}, {%4,%5,%6,%7}, {%8,%9}, {%0,%1,%2,%3};"
        : "+f"(c[0]), "+f"(c[1]), "+f"(c[2]), "+f"(c[3])
        : "r"(a0), "r"(a1), "r"(a2), "r"(a3), "r"(b0), "r"(b1));
}
__device__ __forceinline__ float tanh_fast(float x) {
    float xc = fminf(fmaxf(x, -10.f), 10.f);
    float t  = __expf(2.f * xc);
    return __fdividef(t - 1.f, t + 1.f);
}
__device__ __forceinline__ float quad_sum(float v) {
    v += __shfl_xor_sync(0xffffffffu, v, 1);
    v += __shfl_xor_sync(0xffffffffu, v, 2);
    return v;
}
__device__ __forceinline__ float gelu_exact(float x) {
    return 0.5f * x * (1.f + erff(x * 0.70710678118654752f));
}

// ---------------- launch 0: pre-round emb ----------------
__global__ void preround_kernel(const float* __restrict__ emb)
{
    size_t i = ((size_t)blockIdx.x * 256 + threadIdx.x) * 4;
    float4 x = *(const float4*)(emb + i);
    float4 y;
    y.x = tf32f(x.x); y.y = tf32f(x.y); y.z = tf32f(x.z); y.w = tf32f(x.w);
    *(float4*)(g_et + i) = y;
}

// ---------------- launches 1,2: pack gates weights ----------------
__global__ void pack_a_kernel(const float* __restrict__ Wa)
{
    size_t idx = (size_t)blockIdx.x * 256 + threadIdx.x;
    int n = (int)(idx >> 10);
    int k = (int)(idx & 1023);
    g_wt[idx] = tf32f(Wa[(size_t)(n >> 6) * (EB * DH) + (size_t)k * DH + (n & 63)]);
}
__global__ void pack_bd_kernel(const float* __restrict__ Wb, const float* __restrict__ Wd)
{
    size_t idx = (size_t)blockIdx.x * 256 + threadIdx.x;
    int n = (int)(idx >> 10);
    int k = (int)(idx & 1023);
    float v;
    if (n < 1024) {
        v = Wb[(size_t)(n >> 6) * (EB * DH) + (size_t)k * DH + (n & 63)];
    } else {
        int n2 = n - 1024;
        v = (n2 < 64) ? Wd[(size_t)k * DH + n2] : 0.f;
    }
    g_wt[(size_t)(1024 + n) * 1024 + k] = tf32f(v);
}

// ---------------- launch 3: TF32 gates GEMM (frozen config) ----------------
#define KC 32
#define NKC (GK / KC)
#define ROWB 128
#define TILEB (128 * ROWB)
#define STAGEB (2 * TILEB)
#define GEMM_SMEM (3 * STAGEB)

#define SWZ(row, chunk) ((uint32_t)((row) * ROWB + ((((chunk) ^ (((row) & 1) << 2))) << 4)))

__device__ __forceinline__ void gemm_load_stage(uint32_t sst, int kc, int tid,
                                                const char* Ag, const char* Bg)
{
    const size_t kb = (size_t)kc * 128;
#pragma unroll
    for (int j = 0; j < 4; j++) {
        int id  = tid + j * 256;
        int row = id >> 3;
        int c   = id & 7;
        cp_async16(sst + SWZ(row, c),         Ag + (size_t)row * 4096 + kb + c * 16);
        cp_async16(sst + TILEB + SWZ(row, c), Bg + (size_t)row * 4096 + kb + c * 16);
    }
}

__global__ void __launch_bounds__(256, 2)
gemm_tf32_kernel(const float* __restrict__ ba,
                 const float* __restrict__ bb,
                 const float* __restrict__ bd)
{
    extern __shared__ char sm_raw[];
    const int tid  = threadIdx.x;
    const int wid  = tid >> 5;
    const int lane = tid & 31;
    const uint32_t sbase = smem_u32(sm_raw);

    const long m0 = (long)blockIdx.y * 128;
    const int  n0 = blockIdx.x * 128;
    const int  wm = (wid & 3) * 32;
    const int  wn = (wid >> 2) * 64;

    const char* Ag = (const char*)(g_et + (size_t)m0 * GK);
    const char* Bg = (const char*)(g_wt + (size_t)n0 * GK);

    float acc[2][8][4];
#pragma unroll
    for (int i = 0; i < 2; i++)
#pragma unroll
        for (int j = 0; j < 8; j++)
#pragma unroll
            for (int q = 0; q < 4; q++) acc[i][j][q] = 0.f;

    gemm_load_stage(sbase, 0, tid, Ag, Bg);
    cp_commit();
    gemm_load_stage(sbase + STAGEB, 1, tid, Ag, Bg);
    cp_commit();

    const int lrow4 = lane >> 2;
    const int lch   = lane & 3;

    int stage = 0;
#pragma unroll 3
    for (int kc = 0; kc < NKC; kc++) {
        if (kc + 1 < NKC) {
            asm volatile("cp.async.wait_group 1;" ::: "memory");
        } else {
            asm volatile("cp.async.wait_group 0;" ::: "memory");
        }
        __syncthreads();
        if (kc + 2 < NKC) {
            int nstage = stage + 2; if (nstage >= 3) nstage -= 3;
            gemm_load_stage(sbase + nstage * STAGEB, kc + 2, tid, Ag, Bg);
            cp_commit();
        }

        const char* sA = sm_raw + stage * STAGEB;
        const char* sB = sA + TILEB;

#pragma unroll
        for (int k16 = 0; k16 < 2; k16++) {
            const int ch = k16 * 4 + lch;
            uint32_t aw[2][2][4];
#pragma unroll
            for (int mt = 0; mt < 2; mt++) {
#pragma unroll
                for (int hh = 0; hh < 2; hh++) {
                    int row = wm + mt * 16 + hh * 8 + lrow4;
                    const uint4 v = *(const uint4*)(sA + SWZ(row, ch));
                    aw[mt][hh][0] = v.x;
                    aw[mt][hh][1] = v.y;
                    aw[mt][hh][2] = v.z;
                    aw[mt][hh][3] = v.w;
                }
            }
#pragma unroll
            for (int g = 0; g < 8; g++) {
                int row = wn + g * 8 + lrow4;
                const uint4 bv = *(const uint4*)(sB + SWZ(row, ch));
                mma_tf32(acc[0][g], aw[0][0][0], aw[0][1][0], aw[0][0][1], aw[0][1][1], bv.x, bv.y);
                mma_tf32(acc[0][g], aw[0][0][2], aw[0][1][2], aw[0][0][3], aw[0][1][3], bv.z, bv.w);
                mma_tf32(acc[1][g], aw[1][0][0], aw[1][1][0], aw[1][0][1], aw[1][1][1], bv.x, bv.y);
                mma_tf32(acc[1][g], aw[1][0][2], aw[1][1][2], aw[1][0][3], aw[1][1][3], bv.z, bv.w);
            }
        }
        stage++; if (stage == 3) stage = 0;
    }
    __syncthreads();

    float* sD = (float*)sm_raw;
#pragma unroll
    for (int mt = 0; mt < 2; mt++) {
#pragma unroll
        for (int g = 0; g < 8; g++) {
            int ml = wm + mt * 16 + (lane >> 2);
            int nl = wn + g * 8 + (lane & 3) * 2;
            *(float2*)&sD[ml * 132 + nl]       = make_float2(acc[mt][g][0], acc[mt][g][1]);
            *(float2*)&sD[(ml + 8) * 132 + nl] = make_float2(acc[mt][g][2], acc[mt][g][3]);
        }
    }
    __syncthreads();

    for (int i = tid; i < 128 * 128; i += 256) {
        int mm = i >> 7;
        int nn = i & 127;
        int ng = n0 + nn;
        float c = sD[mm * 132 + nn];
        long m = m0 + mm;
        if (ng < 1024) {
            __stcs(&g_a[m * EB + ng], tanh_fast(c + ba[ng]));
        } else if (ng < 2048) {
            __stcs(&g_b[m * EB + (ng - 1024)], c + bb[ng - 1024]);
        } else if (ng < 2112) {
            __stcs(&g_dx[m * DH + (ng - 2048)], c + bd[ng - 2048]);
        }
    }
}

// ---------------- pack Wc^T + FFN weight transposes (tf32) ----------------
__global__ void pack_wc_kernel(const float* __restrict__ Wc)
{
    int idx = blockIdx.x * 256 + threadIdx.x;   // < 65536
    int h = idx >> 12;
    int e = (idx >> 6) & 63;
    int d = idx & 63;
    g_wc2[idx] = tf32f(Wc[(size_t)h * 4096 + d * 64 + e]);
}
__global__ void pack_ffnw_kernel(const float* __restrict__ W1,
                                 const float* __restrict__ W2,
                                 const float* __restrict__ Wp)
{
    int idx = blockIdx.x * 256 + threadIdx.x;   // < 36864
    if (idx < 16384) {
        int j = idx >> 6, d = idx & 63;
        g_w1t[idx] = tf32f(W1[d * 256 + j]);
    } else if (idx < 32768) {
        int i = idx - 16384;
        int e = i >> 8, j = i & 255;
        g_w2t[i] = tf32f(W2[j * 64 + e]);
    } else {
        int i = idx - 32768;
        int e = i >> 6, d = i & 63;
        g_wpt[i] = tf32f(Wp[d * 64 + e]);
    }
}

// ---------------- chunked scan ----------------
__global__ void __launch_bounds__(512)
scanA_kernel()
{
    const int b = blockIdx.x >> 6;
    const int c = blockIdx.x & 63;
    const int e2 = threadIdx.x;
    size_t base = ((size_t)b * LL + (size_t)c * SCL) * EB + 2 * e2;
    float2 P = make_float2(1.f, 1.f), Q = make_float2(0.f, 0.f);
#pragma unroll 8
    for (int l = 0; l < SCL; l++) {
        size_t idx = base + (size_t)l * EB;
        float2 av = __ldcs((const float2*)(g_a + idx));
        float2 bv = __ldcs((const float2*)(g_b + idx));
        Q.x = fmaf(av.x, Q.x, bv.x);
        Q.y = fmaf(av.y, Q.y, bv.y);
        P.x *= av.x;
        P.y *= av.y;
    }
    const int bh = b * 16 + (e2 >> 5);
    const int d  = (2 * e2) & 63;
    *(float2*)(g_cp + ((size_t)(bh * SCH + c) * 64 + d)) = P;
    *(float2*)(g_cq + ((size_t)(bh * SCH + c) * 64 + d)) = Q;
}

__global__ void __launch_bounds__(512)
scanC_kernel()
{
    const int b = blockIdx.x >> 6;
    const int c = blockIdx.x & 63;
    const int e2 = threadIdx.x;
    const int bh = b * 16 + (e2 >> 5);
    const int d  = (2 * e2) & 63;
    float2 hv = make_float2(0.f, 0.f);
    for (int cc = 0; cc < c; cc++) {
        size_t i = (size_t)(bh * SCH + cc) * 64 + d;
        float2 cp = *(const float2*)(g_cp + i);
        float2 cq = *(const float2*)(g_cq + i);
        hv.x = fmaf(cp.x, hv.x, cq.x);
        hv.y = fmaf(cp.y, hv.y, cq.y);
    }
    size_t base = ((size_t)b * LL + (size_t)c * SCL) * EB + 2 * e2;
#pragma unroll 8
    for (int l = 0; l < SCL; l++) {
        size_t idx = base + (size_t)l * EB;
        float2 av = __ldcs((const float2*)(g_a + idx));
        float2 bv = __ldcs((const float2*)(g_b + idx));
        hv.x = fmaf(av.x, hv.x, bv.x);
        hv.y = fmaf(av.y, hv.y, bv.y);
        float2 hw;
        hw.x = tf32f(hv.x);
        hw.y = tf32f(hv.y);
        __stcs((float2*)(g_hs + idx), hw);
    }
}

// ---------------- gemm2u (unchanged from R16) ----------------
#define G2ROWB 256
#define G2_HS   0
#define G2_WC   32768
#define G2_DX   49152
#define G2_PAR  83968
#define G2U_SMEM 96256
#define SWZ2(row, chunk) ((uint32_t)((row) * G2ROWB + ((((chunk) ^ (((row) & 1) << 2))) << 4)))

__global__ void __launch_bounds__(256, 2)
gemm2u_kernel(const float* __restrict__ bc,  const float* __restrict__ head_w,
              const float* __restrict__ hn_g, const float* __restrict__ hn_b,
              const float* __restrict__ ng,  const float* __restrict__ nb)
{
    extern __shared__ char sm_raw[];
    const int tid  = threadIdx.x;
    const int wid  = tid >> 5;
    const int lane = tid & 31;
    const uint32_t sbase = smem_u32(sm_raw);

    const long t0 = (long)blockIdx.x * 128;
    const int  wm = wid * 16;
    const int  lrow4 = lane >> 2;
    const int  lch   = lane & 3;
    const int  par   = (lrow4 & 1) << 2;

    float* sDx = (float*)(sm_raw + G2_DX);
    float* sBc = (float*)(sm_raw + G2_PAR);
    float* sHg = sBc + 1024;
    float* sHb = sHg + 1024;

    for (int i = tid; i < 1024; i += 256) {
        sBc[i] = bc[i];
        sHg[i] = hn_g[i];
        sHb[i] = hn_b[i];
    }
#pragma unroll
    for (int j = 0; j < 8; j++) {
        int idx = tid + j * 256;
        int row = idx >> 4;
        int c4  = (idx & 15) * 4;
        *(float4*)&sDx[row * 68 + c4] = *(const float4*)(g_dx + (t0 + row) * DH + c4);
    }
    __syncthreads();

    const int rowA = wm + lrow4;

    float sum[8][4];
#pragma unroll
    for (int g = 0; g < 8; g++) {
        int col = g * 8 + lch * 2;
        sum[g][0] = sDx[rowA * 68 + col];
        sum[g][1] = sDx[rowA * 68 + col + 1];
        sum[g][2] = sDx[(rowA + 8) * 68 + col];
        sum[g][3] = sDx[(rowA + 8) * 68 + col + 1];
    }

    for (int h = 0; h < NH; h++) {
#pragma unroll
        for (int j = 0; j < 8; j++) {
            int idx = tid + j * 256;
            int row = idx >> 4;
            int ch  = idx & 15;
            cp_async16(sbase + G2_HS + SWZ2(row, ch),
                       g_hs + (t0 + row) * (size_t)EB + h * 64 + ch * 4);
        }
#pragma unroll
        for (int j = 0; j < 4; j++) {
            int idx = tid + j * 256;
            int row = idx >> 4;
            int ch  = idx & 15;
            cp_async16(sbase + G2_WC + SWZ2(row, ch),
                       g_wc2 + (size_t)h * 4096 + row * 64 + ch * 4);
        }
        cp_commit();
        asm volatile("cp.async.wait_group 0;" ::: "memory");
        __syncthreads();

        float acc[8][4];
#pragma unroll
        for (int g = 0; g < 8; g++)
#pragma unroll
            for (int q = 0; q < 4; q++) acc[g][q] = 0.f;

#pragma unroll
        for (int k16 = 0; k16 < 4; k16++) {
            const int ch = (k16 * 4 + lch) ^ par;
            uint32_t aw[2][4];
#pragma unroll
            for (int hh = 0; hh < 2; hh++) {
                int row = wm + hh * 8 + lrow4;
                const uint4 v = *(const uint4*)(sm_raw + G2_HS + row * G2ROWB + ch * 16);
                aw[hh][0] = v.x; aw[hh][1] = v.y; aw[hh][2] = v.z; aw[hh][3] = v.w;
            }
#pragma unroll
            for (int g = 0; g < 8; g++) {
                int row = g * 8 + lrow4;
                const uint4 bv = *(const uint4*)(sm_raw + G2_WC + row * G2ROWB + ch * 16);
                mma_tf32(acc[g], aw[0][0], aw[1][0], aw[0][1], aw[1][1], bv.x, bv.y);
                mma_tf32(acc[g], aw[0][2], aw[1][2], aw[0][3], aw[1][3], bv.z, bv.w);
            }
        }
        __syncthreads();

        float o[8][4];
        float s1a = 0.f, s2a = 0.f, s1b = 0.f, s2b = 0.f;
#pragma unroll
        for (int g = 0; g < 8; g++) {
            int col = g * 8 + lch * 2;
#pragma unroll
            for (int q = 0; q < 4; q++) {
                int cc = col + (q & 1);
                int rr = (q < 2) ? rowA : (rowA + 8);
                float v = acc[g][q] + sBc[h * 64 + cc] + sDx[rr * 68 + cc];
                o[g][q] = v;
                if (q < 2) { s1a += v; s2a += v * v; }
                else       { s1b += v; s2b += v * v; }
            }
        }
        s1a = quad_sum(s1a); s2a = quad_sum(s2a);
        s1b = quad_sum(s1b); s2b = quad_sum(s2b);
        float meanA = s1a * (1.f / 64.f);
        float rstdA = rsqrtf(s2a * (1.f / 64.f) - meanA * meanA + 1e-5f);
        float meanB = s1b * (1.f / 64.f);
        float rstdB = rsqrtf(s2b * (1.f / 64.f) - meanB * meanB + 1e-5f);
        float hw = head_w[h];
#pragma unroll
        for (int g = 0; g < 8; g++) {
            int col = g * 8 + lch * 2;
#pragma unroll
            for (int q = 0; q < 4; q++) {
                int cc = col + (q & 1);
                float mean = (q < 2) ? meanA : meanB;
                float rstd = (q < 2) ? rstdA : rstdB;
                float lnv = (o[g][q] - mean) * rstd * sHg[h * 64 + cc] + sHb[h * 64 + cc];
                sum[g][q] = fmaf(hw, lnv, sum[g][q]);
            }
        }
    }

    {
        float s1a = 0.f, s2a = 0.f, s1b = 0.f, s2b = 0.f;
#pragma unroll
        for (int g = 0; g < 8; g++)
#pragma unroll
            for (int q = 0; q < 4; q++) {
                sum[g][q] *= (1.f / (float)NH);
                float v = sum[g][q];
                if (q < 2) { s1a += v; s2a += v * v; }
                else       { s1b += v; s2b += v * v; }
            }
        s1a = quad_sum(s1a); s2a = quad_sum(s2a);
        s1b = quad_sum(s1b); s2b = quad_sum(s2b);
        float meanA = s1a * (1.f / 64.f);
        float rstdA = rsqrtf(s2a * (1.f / 64.f) - meanA * meanA + 1e-5f);
        float meanB = s1b * (1.f / 64.f);
        float rstdB = rsqrtf(s2b * (1.f / 64.f) - meanB * meanB + 1e-5f);
        __syncthreads();
#pragma unroll
        for (int g = 0; g < 8; g++) {
            int col = g * 8 + lch * 2;
#pragma unroll
            for (int q = 0; q < 4; q++) {
                int cc = col + (q & 1);
                float mean = (q < 2) ? meanA : meanB;
                float rstd = (q < 2) ? rstdA : rstdB;
                int rr = (q < 2) ? rowA : (rowA + 8);
                float z = sum[g][q];
                sDx[rr * 68 + cc] = z + (z - mean) * rstd * ng[cc] + nb[cc];
            }
        }
    }
    __syncthreads();

#pragma unroll
    for (int j = 0; j < 8; j++) {
        int idx = tid + j * 256;
        int row = idx >> 4;
        int c4  = (idx & 15) * 4;
        __stcs((float4*)(g_u + (t0 + row) * DH + c4), *(const float4*)&sDx[row * 68 + c4]);
    }
}

// ---------------- ffn: tensor-core FFN + projection ----------------
// per 128-token tile: mid = u@W1T (+b1, gelu) in 2 chunks of 128;
// acc2 += P@W2T; ho = u + acc2 + b2; out = ho@WpT + bp.
// smem: sU [128 x 256B] @0 (32KB), sP [128 x 512B] @32KB (64KB) = 96KB.
#define FU_ROWB 256
#define FP_ROWB 512
#define F_SP 32768
#define FFN_SMEM 98304

__global__ void __launch_bounds__(256, 2)
ffn_kernel(const float* __restrict__ b1, const float* __restrict__ b2,
           const float* __restrict__ bp, float* __restrict__ out)
{
    extern __shared__ char sm_raw[];
    const int tid  = threadIdx.x;
    const int wid  = tid >> 5;
    const int lane = tid & 31;

    const long t0 = (long)blockIdx.x * 128;
    const int lrow4 = lane >> 2;
    const int lch   = lane & 3;
    const int par   = (lrow4 & 1) << 2;
    const int wm  = (wid & 3) * 32;
    const int wn  = (wid >> 2) * 64;   // stage1 (N=128 chunk)
    const int wn2 = (wid >> 2) * 32;   // stages 2/4 (N=64)

    // load u -> sU (tf32-rounded)
#pragma unroll
    for (int j = 0; j < 8; j++) {
        int idx = tid + j * 256;
        int row = idx >> 4;
        int ch  = idx & 15;
        float4 v = *(const float4*)(g_u + (t0 + row) * DH + ch * 4);
        v.x = tf32f(v.x); v.y = tf32f(v.y); v.z = tf32f(v.z); v.w = tf32f(v.w);
        *(float4*)(sm_raw + row * FU_ROWB + ((ch ^ ((row & 1) << 2)) << 4)) = v;
    }
    __syncthreads();

    float acc2[2][4][4];
#pragma unroll
    for (int mt = 0; mt < 2; mt++)
#pragma unroll
        for (int g = 0; g < 4; g++)
#pragma unroll
            for (int q = 0; q < 4; q++) acc2[mt][g][q] = 0.f;

    for (int jc = 0; jc < 2; jc++) {
        // ---- stage 1: mid chunk = u @ W1T[jc] ----
        float acc1[2][8][4];
#pragma unroll
        for (int mt = 0; mt < 2; mt++)
#pragma unroll
            for (int g = 0; g < 8; g++)
#pragma unroll
                for (int q = 0; q < 4; q++) acc1[mt][g][q] = 0.f;

#pragma unroll
        for (int k16 = 0; k16 < 4; k16++) {
            const int pc = (k16 * 4 + lch) ^ par;
            uint32_t aw[2][2][4];
#pragma unroll
            for (int mt = 0; mt < 2; mt++)
#pragma unroll
                for (int hh = 0; hh < 2; hh++) {
                    int row = wm + mt * 16 + hh * 8 + lrow4;
                    const uint4 v = *(const uint4*)(sm_raw + row * FU_ROWB + pc * 16);
                    aw[mt][hh][0] = v.x; aw[mt][hh][1] = v.y;
                    aw[mt][hh][2] = v.z; aw[mt][hh][3] = v.w;
                }
#pragma unroll
            for (int g = 0; g < 8; g++) {
                const uint4 bv = *(const uint4*)(g_w1t + (jc * 128 + wn + g * 8 + lrow4) * 64
                                                       + (k16 * 4 + lch) * 4);
                mma_tf32(acc1[0][g], aw[0][0][0], aw[0][1][0], aw[0][0][1], aw[0][1][1], bv.x, bv.y);
                mma_tf32(acc1[0][g], aw[0][0][2], aw[0][1][2], aw[0][0][3], aw[0][1][3], bv.z, bv.w);
                mma_tf32(acc1[1][g], aw[1][0][0], aw[1][1][0], aw[1][0][1], aw[1][1][1], bv.x, bv.y);
                mma_tf32(acc1[1][g], aw[1][0][2], aw[1][1][2], aw[1][0][3], aw[1][1][3], bv.z, bv.w);
            }
        }
        __syncthreads();   // prior stage-2 reads of sP complete

        // gelu + stage tf32 to sP
#pragma unroll
        for (int mt = 0; mt < 2; mt++)
#pragma unroll
            for (int g = 0; g < 8; g++) {
                int row = wm + mt * 16 + (lane >> 2);
                int col = wn + g * 8 + (lane & 3) * 2;
                float bb1 = b1[jc * 128 + col];
                float bb2 = b1[jc * 128 + col + 1];
                float2 v0, v1;
                v0.x = tf32f(gelu_exact(acc1[mt][g][0] + bb1));
                v0.y = tf32f(gelu_exact(acc1[mt][g][1] + bb2));
                v1.x = tf32f(gelu_exact(acc1[mt][g][2] + bb1));
                v1.y = tf32f(gelu_exact(acc1[mt][g][3] + bb2));
                uint32_t a0 = F_SP + row * FP_ROWB + (((col >> 2) ^ ((row & 1) << 2)) << 4) + (col & 3) * 4;
                int row1 = row + 8;
                uint32_t a1 = F_SP + row1 * FP_ROWB + (((col >> 2) ^ ((row1 & 1) << 2)) << 4) + (col & 3) * 4;
                *(float2*)(sm_raw + a0) = v0;
                *(float2*)(sm_raw + a1) = v1;
            }
        __syncthreads();

        // ---- stage 2 partial: acc2 += P @ W2T[:, jc] ----
#pragma unroll
        for (int k16 = 0; k16 < 8; k16++) {
            const int pc = (k16 * 4 + lch) ^ par;
            uint32_t aw[2][2][4];
#pragma unroll
            for (int mt = 0; mt < 2; mt++)
#pragma unroll
                for (int hh = 0; hh < 2; hh++) {
                    int row = wm + mt * 16 + hh * 8 + lrow4;
                    const uint4 v = *(const uint4*)(sm_raw + F_SP + row * FP_ROWB + pc * 16);
                    aw[mt][hh][0] = v.x; aw[mt][hh][1] = v.y;
                    aw[mt][hh][2] = v.z; aw[mt][hh][3] = v.w;
                }
#pragma unroll
            for (int g = 0; g < 4; g++) {
                const uint4 bv = *(const uint4*)(g_w2t + (wn2 + g * 8 + lrow4) * 256
                                                       + jc * 128 + (k16 * 4 + lch) * 4);
                mma_tf32(acc2[0][g], aw[0][0][0], aw[0][1][0], aw[0][0][1], aw[0][1][1], bv.x, bv.y);
                mma_tf32(acc2[0][g], aw[0][0][2], aw[0][1][2], aw[0][0][3], aw[0][1][3], bv.z, bv.w);
                mma_tf32(acc2[1][g], aw[1][0][0], aw[1][1][0], aw[1][0][1], aw[1][1][1], bv.x, bv.y);
                mma_tf32(acc2[1][g], aw[1][0][2], aw[1][1][2], aw[1][0][3], aw[1][1][3], bv.z, bv.w);
            }
        }
    }
    __syncthreads();

    // ---- stage 3: ho = u + acc2 + b2 -> sHo (sP region, tf32) ----
#pragma unroll
    for (int mt = 0; mt < 2; mt++)
#pragma unroll
        for (int g = 0; g < 4; g++) {
            int row = wm + mt * 16 + (lane >> 2);
            int col = wn2 + g * 8 + (lane & 3) * 2;
            float bb1 = b2[col], bb2 = b2[col + 1];
            float2 u0 = *(const float2*)(g_u + (t0 + row) * DH + col);
            int row1 = row + 8;
            float2 u1 = *(const float2*)(g_u + (t0 + row1) * DH + col);
            float2 v0, v1;
            v0.x = tf32f(acc2[mt][g][0] + bb1 + u0.x);
            v0.y = tf32f(acc2[mt][g][1] + bb2 + u0.y);
            v1.x = tf32f(acc2[mt][g][2] + bb1 + u1.x);
            v1.y = tf32f(acc2[mt][g][3] + bb2 + u1.y);
            uint32_t a0 = F_SP + row * FP_ROWB + (((col >> 2) ^ ((row & 1) << 2)) << 4) + (col & 3) * 4;
            uint32_t a1 = F_SP + row1 * FP_ROWB + (((col >> 2) ^ ((row1 & 1) << 2)) << 4) + (col & 3) * 4;
            *(float2*)(sm_raw + a0) = v0;
            *(float2*)(sm_raw + a1) = v1;
        }
    __syncthreads();

    // ---- stage 4: out = ho @ WpT + bp ----
    float acc3[2][4][4];
#pragma unroll
    for (int mt = 0; mt < 2; mt++)
#pragma unroll
        for (int g = 0; g < 4; g++)
#pragma unroll
            for (int q = 0; q < 4; q++) acc3[mt][g][q] = 0.f;

#pragma unroll
    for (int k16 = 0; k16 < 4; k16++) {
        const int pc = (k16 * 4 + lch) ^ par;
        uint32_t aw[2][2][4];
#pragma unroll
        for (int mt = 0; mt < 2; mt++)
#pragma unroll
            for (int hh = 0; hh < 2; hh++) {
                int row = wm + mt * 16 + hh * 8 + lrow4;
                const uint4 v = *(const uint4*)(sm_raw + F_SP + row * FP_ROWB + pc * 16);
                aw[mt][hh][0] = v.x; aw[mt][hh][1] = v.y;
                aw[mt][hh][2] = v.z; aw[mt][hh][3] = v.w;
            }
#pragma unroll
        for (int g = 0; g < 4; g++) {
            const uint4 bv = *(const uint4*)(g_wpt + (wn2 + g * 8 + lrow4) * 64
                                                   + (k16 * 4 + lch) * 4);
            mma_tf32(acc3[0][g], aw[0][0][0], aw[0][1][0], aw[0][0][1], aw[0][1][1], bv.x, bv.y);
            mma_tf32(acc3[0][g], aw[0][0][2], aw[0][1][2], aw[0][0][3], aw[0][1][3], bv.z, bv.w);
            mma_tf32(acc3[1][g], aw[1][0][0], aw[1][1][0], aw[1][0][1], aw[1][1][1], bv.x, bv.y);
            mma_tf32(acc3[1][g], aw[1][0][2], aw[1][1][2], aw[1][0][3], aw[1][1][3], bv.z, bv.w);
        }
    }

#pragma unroll
    for (int mt = 0; mt < 2; mt++)
#pragma unroll
        for (int g = 0; g < 4; g++) {
            int row = wm + mt * 16 + (lane >> 2);
            int col = wn2 + g * 8 + (lane & 3) * 2;
            float bb1 = bp[col], bb2 = bp[col + 1];
            *(float2*)(out + (t0 + row) * DH + col) =
                make_float2(acc3[mt][g][0] + bb1, acc3[mt][g][1] + bb2);
            *(float2*)(out + (t0 + row + 8) * DH + col) =
                make_float2(acc3[mt][g][2] + bb1, acc3[mt][g][3] + bb2);
        }
}

// ---------------- launch ----------------
extern "C" void kernel_launch(void* const* d_in, const int* in_sizes, int n_in,
                              void* d_out, int out_size)
{
    const float* emb    = (const float*)d_in[0];
    const float* Wa     = (const float*)d_in[1];
    const float* ba     = (const float*)d_in[2];
    const float* Wb     = (const float*)d_in[3];
    const float* bb     = (const float*)d_in[4];
    const float* Wc     = (const float*)d_in[5];
    const float* bc     = (const float*)d_in[6];
    const float* head_w = (const float*)d_in[7];
    const float* hn_g   = (const float*)d_in[8];
    const float* hn_b   = (const float*)d_in[9];
    const float* Wd     = (const float*)d_in[10];
    const float* bd     = (const float*)d_in[11];
    const float* W1     = (const float*)d_in[12];
    const float* b1     = (const float*)d_in[13];
    const float* W2     = (const float*)d_in[14];
    const float* b2     = (const float*)d_in[15];
    const float* Wp     = (const float*)d_in[16];
    const float* bp     = (const float*)d_in[17];
    const float* ng     = (const float*)d_in[18];
    const float* nb     = (const float*)d_in[19];
    float* out = (float*)d_out;

    cudaFuncSetAttribute(gemm_tf32_kernel, cudaFuncAttributeMaxDynamicSharedMemorySize, GEMM_SMEM);
    cudaFuncSetAttribute(gemm2u_kernel, cudaFuncAttributeMaxDynamicSharedMemorySize, G2U_SMEM);
    cudaFuncSetAttribute(ffn_kernel, cudaFuncAttributeMaxDynamicSharedMemorySize, FFN_SMEM);

    preround_kernel<<<(int)((size_t)MT * GK / 4 / 256), 256>>>(emb);
    pack_a_kernel<<<4096, 256>>>(Wa);
    pack_bd_kernel<<<4608, 256>>>(Wb, Wd);

    dim3 ggrid(GNP / 128, MT / 128);
    gemm_tf32_kernel<<<ggrid, 256, GEMM_SMEM>>>(ba, bb, bd);

    pack_wc_kernel<<<256, 256>>>(Wc);
    pack_ffnw_kernel<<<144, 256>>>(W1, W2, Wp);
    scanA_kernel<<<BB * SCH, 512>>>();
    scanC_kernel<<<BB * SCH, 512>>>();

    gemm2u_kernel<<<MT / 128, 256, G2U_SMEM>>>(bc, head_w, hn_g, hn_b, ng, nb);

    ffn_kernel<<<MT / 128, 256, FFN_SMEM>>>(b1, b2, bp, out);
}